// round 14
// baseline (speedup 1.0000x reference)
#include <cuda_runtime.h>
#include <cuda_fp16.h>
#include <cuda_bf16.h>
#include <math.h>
#include <stdint.h>

typedef unsigned long long ull;

// ---------------- problem constants ----------------
#define B   64
#define T   256
#define D   2048
#define H   1024
#define G3  3072
#define NC  1000
#define BT  (B*T)

#define FMA_F32X2(acc, a, b) \
    asm("fma.rn.f32x2 %0, %1, %2, %0;" : "+l"(acc) : "l"(a), "l"(b))

#define CP_ASYNC16(dst, src) \
    asm volatile("cp.async.cg.shared.global [%0], [%1], 16;" :: "r"(dst), "l"(src))
#define CP_COMMIT() asm volatile("cp.async.commit_group;")
#define CP_WAITN(n) asm volatile("cp.async.wait_group %0;" :: "n"(n))
#define CP_WAIT0()  asm volatile("cp.async.wait_group 0;")

__device__ __forceinline__ float f2lo(ull v) { return __uint_as_float((unsigned)(v & 0xffffffffULL)); }
__device__ __forceinline__ float f2hi(ull v) { return __uint_as_float((unsigned)(v >> 32)); }

// ---------------- warp MMA helpers ----------------
__device__ __forceinline__ void ldsm_x4(uint32_t* r, unsigned addr) {
    asm volatile("ldmatrix.sync.aligned.m8n8.x4.shared.b16 {%0,%1,%2,%3}, [%4];"
        : "=r"(r[0]), "=r"(r[1]), "=r"(r[2]), "=r"(r[3]) : "r"(addr));
}
__device__ __forceinline__ void ldsm_x2(uint32_t* r, unsigned addr) {
    asm volatile("ldmatrix.sync.aligned.m8n8.x2.shared.b16 {%0,%1}, [%2];"
        : "=r"(r[0]), "=r"(r[1]) : "r"(addr));
}
__device__ __forceinline__ void mma_fp16(float* c, const uint32_t* a, const uint32_t* b) {
    asm volatile(
        "mma.sync.aligned.m16n8k16.row.col.f32.f16.f16.f32 "
        "{%0,%1,%2,%3}, {%4,%5,%6,%7}, {%8,%9}, {%0,%1,%2,%3};"
        : "+f"(c[0]), "+f"(c[1]), "+f"(c[2]), "+f"(c[3])
        : "r"(a[0]), "r"(a[1]), "r"(a[2]), "r"(a[3]), "r"(b[0]), "r"(b[1]));
}

// ---------------- device scratch ----------------
__device__ __align__(16) float  g_M2 [3*2048];
__device__ __align__(16) float  g_M34[3*16384];               // [g][k(256)][n(64)] fp32
__device__ __align__(16) __half g_M34h[3*16384];              // [g][n][k] fp16 hi
__device__ __align__(16) __half g_M34l[3*16384];              // [g][n][k] fp16 lo
__device__ __align__(16) __half g_UTf[(size_t)G3*H];          // U^T fp16 [j][k]
__device__ __align__(16) __half g_P  [(size_t)BT*12288];
__device__ __align__(16) float  g_gi [(size_t)BT*G3];         // [t][b][3H]
__device__ __align__(16) __half g_hh[2][B*H];                 // hidden hi fp16 (ping-pong)
__device__ __align__(16) __half g_hl[2][B*H];                 // hidden lo fp16 (x1024), carry only
// tree barrier: 8 leaf counters (128B apart), one root, one generation word
__device__ unsigned g_leaf[16*32];
__device__ unsigned g_root;
__device__ unsigned g_gen;

// ---------------- init ----------------
__global__ void init_kernel() {
    int idx = blockIdx.x * blockDim.x + threadIdx.x;
    unsigned* hh = (unsigned*)g_hh[0];
    unsigned* hl = (unsigned*)g_hl[0];
    for (int i = idx; i < B*H/2; i += gridDim.x * blockDim.x) { hh[i] = 0u; hl[i] = 0u; }
    if (idx < 16*32) g_leaf[idx] = 0u;
    if (idx == 0) { g_root = 0u; g_gen = 0u; }
}

// ---------------- build M2, M34 (grid-parallel) ----------------
__global__ void build_M_kernel(const float* __restrict__ c0,
                               const float* __restrict__ c1,
                               const float* __restrict__ c2,
                               const float* __restrict__ c3) {
    int gid = blockIdx.x * blockDim.x + threadIdx.x;
    int nt  = gridDim.x * blockDim.x;
    for (int idx = gid; idx < 3*2048; idx += nt) {
        int r2 = idx & 3, o2 = (idx>>2)&3, o1 = (idx>>4)&3;
        int i2 = (idx>>6)&7, i1 = (idx>>9)&3, g = idx>>11;
        float s = 0.f;
        #pragma unroll
        for (int r1 = 0; r1 < 4; ++r1)
            s += c0[g*64 + i1*16 + o1*4 + r1] *
                 c1[g*512 + r1*128 + i2*16 + o2*4 + r2];
        g_M2[idx] = s;
    }
    for (int idx = gid; idx < 3*16384; idx += nt) {
        int o4 = idx & 7, o3 = (idx>>3)&7, i4 = (idx>>6)&7;
        int i3 = (idx>>9)&7, r2 = (idx>>12)&3, g = idx>>14;
        float s = 0.f;
        #pragma unroll
        for (int r3 = 0; r3 < 4; ++r3)
            s += c2[g*1024 + r2*256 + i3*32 + o3*4 + r3] *
                 c3[g*256  + r3*64  + i4*8  + o4];
        g_M34[idx] = s;
    }
}

// transpose M34 to [g][n][k] fp16 hi/lo (separate kernel: needs g_M34 complete)
__global__ void build_M34T_kernel() {
    int gid = blockIdx.x * blockDim.x + threadIdx.x;
    int nt  = gridDim.x * blockDim.x;
    for (int idx = gid; idx < 3*16384; idx += nt) {
        int g = idx >> 14, rem = idx & 16383;
        int n = rem >> 8, k = rem & 255;
        float v = g_M34[g*16384 + k*64 + n];
        __half hi = __float2half_rn(v);
        g_M34h[idx] = hi;
        g_M34l[idx] = __float2half_rn(v - __half2float(hi));
    }
}

// ---------------- transpose U [H,G3] -> UT fp16 [G3,H] ----------------
__global__ void build_UT_kernel(const float* __restrict__ U) {
    __shared__ float s[32][33];
    int j0 = blockIdx.x * 32;
    int k0 = blockIdx.y * 32;
    int tx = threadIdx.x, ty = threadIdx.y;
    #pragma unroll
    for (int r = ty; r < 32; r += 8)
        s[r][tx] = U[(size_t)(k0 + r) * G3 + j0 + tx];
    __syncthreads();
    #pragma unroll
    for (int r = ty; r < 32; r += 8)
        g_UTf[(size_t)(j0 + r) * H + k0 + tx] = __float2half_rn(s[tx][r]);
}

// ---------------- TT stage A (FMA2, at its issue ceiling) ----------------
#define TTA_SMEM (32*192*8 + 16*2048*4)   // 180224
__global__ void __launch_bounds__(256)
ttA_kernel(const float* __restrict__ X) {
    extern __shared__ __align__(16) float smA[];
    float2* sM = (float2*)smA;                 // [k(32)][r(192)] duplicated
    float*  sV = smA + 2*32*192;               // [bt(16)][2048]

    const int tid = threadIdx.x;
    const int bt0 = blockIdx.x * 16;

    for (int i = tid; i < 32*192; i += 256) {
        int k = i / 192, r = i - k*192;
        int g = r >> 6, ocr = r & 63;
        float v = g_M2[g*2048 + k*64 + ocr];
        sM[i] = make_float2(v, v);
    }
    {
        const float4* Xb = (const float4*)(X + (size_t)bt0 * D);
        float4* sv4 = (float4*)sV;
        #pragma unroll 8
        for (int q = 0; q < 32; ++q) sv4[tid + q*256] = Xb[tid + q*256];
    }
    __syncthreads();

    const int wid = tid >> 5, l = tid & 31;
    const int bts = wid*2 + (l >> 4);
    const int pq  = l & 15;
    const float* vb = sV + bts*2048 + pq*4;
    __half* Pb = g_P + (size_t)(bt0 + bts) * 12288;

    for (int rp = 0; rp < 12; ++rp) {
        const int r0 = rp * 16;
        ull acc[16][2];
        #pragma unroll
        for (int r = 0; r < 16; ++r) { acc[r][0] = 0ULL; acc[r][1] = 0ULL; }

        #pragma unroll 4
        for (int k = 0; k < 32; ++k) {
            ulonglong2 vv = *(const ulonglong2*)(vb + k*64);
            const ulonglong2* mrow = (const ulonglong2*)(sM + k*192 + r0);
            #pragma unroll
            for (int m = 0; m < 8; ++m) {
                ulonglong2 mm = mrow[m];
                FMA_F32X2(acc[2*m  ][0], vv.x, mm.x);
                FMA_F32X2(acc[2*m  ][1], vv.y, mm.x);
                FMA_F32X2(acc[2*m+1][0], vv.x, mm.y);
                FMA_F32X2(acc[2*m+1][1], vv.y, mm.y);
            }
        }
        #pragma unroll
        for (int rr = 0; rr < 16; ++rr) {
            int r = r0 + rr;
            int g = r >> 6, o = (r >> 2) & 15, r2 = r & 3;
            __half2 hA = __floats2half2_rn(f2lo(acc[rr][0]), f2hi(acc[rr][0]));
            __half2 hB = __floats2half2_rn(f2lo(acc[rr][1]), f2hi(acc[rr][1]));
            __half2* d2 = (__half2*)(Pb + ((size_t)(g*16 + o))*256 + r2*64 + pq*4);
            d2[0] = hA; d2[1] = hB;
        }
    }
}

// ---------------- TT stage B: HMMA ----------------
#define TTB_SMEM (65536 + 32768 + 32768)   // A 64KB | Bh 32KB | Bl 32KB
__global__ void __launch_bounds__(256)
ttB_kernel(const float* __restrict__ bi) {
    extern __shared__ __align__(1024) char smB[];
    const unsigned sb = (unsigned)__cvta_generic_to_shared(smB);
    const int tid = threadIdx.x;
    const int g   = blockIdx.y;
    const int m0  = blockIdx.x * 128;

    for (int i = tid; i < 4096; i += 256) {
        int r = i >> 5, u = i & 31;
        int us = (u & ~7) | ((u & 7) ^ (r & 7));
        int m = m0 + r;
        const __half* src = g_P + ((size_t)(m >> 4)*48 + g*16 + (m & 15))*256 + u*8;
        CP_ASYNC16(sb + (unsigned)(r*512 + us*16), src);
    }
    for (int i = tid; i < 2048; i += 256) {
        int n = i >> 5, u = i & 31;
        int us = (u & ~7) | ((u & 7) ^ (n & 7));
        const __half* s1 = g_M34h + ((size_t)g*64 + n)*256 + u*8;
        const __half* s2 = g_M34l + ((size_t)g*64 + n)*256 + u*8;
        CP_ASYNC16(sb + 65536u + (unsigned)(n*512 + us*16), s1);
        CP_ASYNC16(sb + 98304u + (unsigned)(n*512 + us*16), s2);
    }
    CP_COMMIT(); CP_WAIT0();
    __syncthreads();

    const int wid = tid >> 5, lane = tid & 31;
    const int wm = wid & 3, wn = wid >> 2;
    const int lrow = lane & 15, lk = lane >> 4;

    float c[2][4][4];
    #pragma unroll
    for (int ms = 0; ms < 2; ++ms)
        #pragma unroll
        for (int j = 0; j < 4; ++j)
            #pragma unroll
            for (int e = 0; e < 4; ++e) c[ms][j][e] = 0.f;

    #pragma unroll
    for (int ks = 0; ks < 16; ++ks) {
        const int u = ks*2 + lk;
        uint32_t a[2][4], bh4[2][4], bl4[2][4];
        #pragma unroll
        for (int ms = 0; ms < 2; ++ms) {
            int r = wm*32 + ms*16 + lrow;
            int us = (u & ~7) | ((u & 7) ^ (r & 7));
            ldsm_x4(a[ms], sb + (unsigned)(r*512 + us*16));
        }
        #pragma unroll
        for (int ns = 0; ns < 2; ++ns) {
            int n = wn*32 + ns*16 + lrow;
            int us = (u & ~7) | ((u & 7) ^ (n & 7));
            ldsm_x4(bh4[ns], sb + 65536u + (unsigned)(n*512 + us*16));
            ldsm_x4(bl4[ns], sb + 98304u + (unsigned)(n*512 + us*16));
        }
        #pragma unroll
        for (int ms = 0; ms < 2; ++ms)
            #pragma unroll
            for (int j = 0; j < 4; ++j) {
                uint32_t bfh[2] = { bh4[j>>1][j&1], bh4[j>>1][(j&1)+2] };
                uint32_t bfl[2] = { bl4[j>>1][j&1], bl4[j>>1][(j&1)+2] };
                mma_fp16(c[ms][j], a[ms], bfh);
                mma_fp16(c[ms][j], a[ms], bfl);
            }
    }

    #pragma unroll
    for (int ms = 0; ms < 2; ++ms) {
        #pragma unroll
        for (int j = 0; j < 4; ++j) {
            int nn = wn*32 + j*8 + (lane & 3)*2;
            #pragma unroll
            for (int half = 0; half < 2; ++half) {
                int r = wm*32 + ms*16 + (lane >> 2) + half*8;
                int m = m0 + r;
                int bt = m >> 4, oo = m & 15;
                int bb = bt >> 8, tt = bt & 255;
                const float* bp = bi + g*1024 + oo*64 + nn;
                float2 v;
                v.x = c[ms][j][half*2]     + bp[0];
                v.y = c[ms][j][half*2 + 1] + bp[1];
                *(float2*)(g_gi + ((size_t)tt*B + bb)*G3 + g*1024 + oo*64 + nn) = v;
            }
        }
    }
}

// ---------------- persistent mma.sync scan: 64 blocks x 768 thr ----------------
// Each block owns 16 o's. 24 warps = 4 M-tiles(16 b) x 6 n8-tiles (48 B-rows = 3g x 16o).
// h MMA operand: single fp16 (hi); carry fp16 hi+lo in global.
// All 4 K-chunks staged up-front per step (4 commit groups).
#define SCAN_BLOCKS 64
#define SCAN_THREADS 768
#define SC_B  0                      // 48 x 2048B (U fp16, swizzled)
#define SC_A  98304                  // 4 chunks x 32768
#define SCAN_SMEM (98304 + 131072)   // 229376
#define RED_STRIDE 65                // red[n(48)][RED_STRIDE]

__device__ __forceinline__ void stageA_chunk(const __half* hh, unsigned sb, int ck, int tid) {
    const unsigned base = sb + (unsigned)SC_A + (unsigned)ck*32768u;
    for (int i = tid; i < 2048; i += SCAN_THREADS) {
        int b = i >> 5, u = i & 31;
        int us = (u & ~7) | ((u & 7) ^ (b & 7));
        CP_ASYNC16(base + (unsigned)(b*512 + us*16), hh + (size_t)b*H + ck*256 + u*8);
    }
    CP_COMMIT();
}

__global__ void __launch_bounds__(SCAN_THREADS, 1)
scan_kernel(const float* __restrict__ bh) {
    extern __shared__ __align__(1024) char smem[];
    const unsigned sb = (unsigned)__cvta_generic_to_shared(smem);
    const int tid  = threadIdx.x;
    const int wid  = tid >> 5;
    const int lane = tid & 31;
    const int o0   = blockIdx.x * 16;
    const int wm   = wid & 3;            // M-tile (batches wm*16..+15)
    const int wn   = wid >> 2;           // n8-tile (0..5) over 48 B-rows
    const int leaf = blockIdx.x >> 3;    // 8 leaves of 8 blocks

    // stage B = UT slice fp16 (rows n = g*16+ol), swizzled for ldmatrix
    for (int i = tid; i < 48*128; i += SCAN_THREADS) {
        int n = i >> 7, u = i & 127;
        int us = (u & ~7) | ((u & 7) ^ (n & 7));
        int g = n >> 4, ol = n & 15;
        size_t src = ((size_t)(g*H + o0 + ol))*H + (size_t)u*8;
        *(uint4*)(smem + SC_B + n*2048 + us*16) = *(const uint4*)(g_UTf + src);
    }
    __syncthreads();

    const int arow   = wm*16 + (lane & 15);
    const int kadd8  = lane >> 4;
    const unsigned arow_off = (unsigned)(arow * 512);
    const int arow7  = arow & 7;
    const int brow   = wn*8 + (lane & 7);
    const unsigned brow_off = (unsigned)(brow * 2048);
    const int brow7  = brow & 7;
    const int bk8    = (lane >> 3) & 1;

    // pointwise outputs: p0 = tid (b 0..47), p1 = 768+tid for tid<256 (b 48..63)
    const int b0o = tid >> 4,          ol0 = tid & 15;
    const int b1o = (tid + 768) >> 4,  ol1 = tid & 15;
    float bh0v[3], bh1v[3];
    #pragma unroll
    for (int g = 0; g < 3; ++g) {
        bh0v[g] = bh[g*H + o0 + ol0];
        bh1v[g] = bh[g*H + o0 + ol1];
    }

    float* red = (float*)(smem + SC_A);       // [48][RED_STRIDE] fp32, aliases A chunk 0

    for (int t = 0; t < T; ++t) {
        const __half* hh = g_hh[t & 1];
        const __half* hl = g_hl[t & 1];
        __half* nhh = g_hh[(t & 1) ^ 1];
        __half* nhl = g_hl[(t & 1) ^ 1];

        // stage ALL 4 chunks (4 async groups)
        stageA_chunk(hh, sb, 0, tid);
        stageA_chunk(hh, sb, 1, tid);
        stageA_chunk(hh, sb, 2, tid);
        stageA_chunk(hh, sb, 3, tid);

        float gi0[3], gi1[3], hold0, hold1;
        {
            const float* gp0 = g_gi + ((size_t)t*B + b0o)*G3 + o0 + ol0;
            #pragma unroll
            for (int g = 0; g < 3; ++g) gi0[g] = __ldg(gp0 + g*H);
            hold0 = __half2float(hh[(size_t)b0o*H + o0 + ol0])
                  + __half2float(hl[(size_t)b0o*H + o0 + ol0]) * 9.765625e-4f;
            if (tid < 256) {
                const float* gp1 = g_gi + ((size_t)t*B + b1o)*G3 + o0 + ol1;
                #pragma unroll
                for (int g = 0; g < 3; ++g) gi1[g] = __ldg(gp1 + g*H);
                hold1 = __half2float(hh[(size_t)b1o*H + o0 + ol1])
                      + __half2float(hl[(size_t)b1o*H + o0 + ol1]) * 9.765625e-4f;
            }
        }

        float c[4] = {0.f, 0.f, 0.f, 0.f};

        #define SCAN_CHUNK(CK, PEND)                                           \
        {                                                                      \
            CP_WAITN(PEND);                                                    \
            __syncthreads();                                                   \
            const unsigned aB = sb + (unsigned)SC_A + (unsigned)(CK*32768);    \
            _Pragma("unroll")                                                  \
            for (int ks = 0; ks < 16; ++ks) {                                  \
                uint32_t ah[4], br[2];                                         \
                int u  = ks*2 + kadd8;                                         \
                int us = (u & ~7) | ((u & 7) ^ arow7);                         \
                ldsm_x4(ah, aB + arow_off + (unsigned)(us*16));                \
                int kg  = CK*32 + ks*2 + bk8;                                  \
                int bus = (kg & ~7) | ((kg & 7) ^ brow7);                      \
                ldsm_x2(br, sb + (unsigned)SC_B + brow_off + (unsigned)(bus*16)); \
                mma_fp16(c, ah, br);                                           \
            }                                                                  \
        }
        SCAN_CHUNK(0, 3)
        SCAN_CHUNK(1, 2)
        SCAN_CHUNK(2, 1)
        SCAN_CHUNK(3, 0)
        #undef SCAN_CHUNK

        // scatter C frags to red[n][b]  (red aliases chunk 0; all reads done)
        __syncthreads();
        {
            int row = wm*16 + (lane >> 2);
            int n0  = wn*8 + (lane & 3)*2;
            red[(n0    )*RED_STRIDE + row]     = c[0];
            red[(n0 + 1)*RED_STRIDE + row]     = c[1];
            red[(n0    )*RED_STRIDE + row + 8] = c[2];
            red[(n0 + 1)*RED_STRIDE + row + 8] = c[3];
        }
        __syncthreads();

        // pointwise GRU update
        {
            float s0 = red[(       ol0)*RED_STRIDE + b0o];
            float s1 = red[(16   + ol0)*RED_STRIDE + b0o];
            float s2 = red[(32   + ol0)*RED_STRIDE + b0o];
            float r  = 1.f / (1.f + __expf(-(gi0[0] + s0 + bh0v[0])));
            float z  = 1.f / (1.f + __expf(-(gi0[1] + s1 + bh0v[1])));
            float na = gi0[2] + r * (s2 + bh0v[2]);
            float te = __expf(2.f * na);
            float n  = 1.f - 2.f / (te + 1.f);
            float hn = (1.f - z) * n + z * hold0;
            __half hb = __float2half_rn(hn);
            nhh[(size_t)b0o*H + o0 + ol0] = hb;
            nhl[(size_t)b0o*H + o0 + ol0] = __float2half_rn((hn - __half2float(hb)) * 1024.f);
            if (tid < 256) {
                float q0 = red[(       ol1)*RED_STRIDE + b1o];
                float q1 = red[(16   + ol1)*RED_STRIDE + b1o];
                float q2 = red[(32   + ol1)*RED_STRIDE + b1o];
                float r1 = 1.f / (1.f + __expf(-(gi1[0] + q0 + bh1v[0])));
                float z1 = 1.f / (1.f + __expf(-(gi1[1] + q1 + bh1v[1])));
                float nb = gi1[2] + r1 * (q2 + bh1v[2]);
                float t2 = __expf(2.f * nb);
                float n1 = 1.f - 2.f / (t2 + 1.f);
                float h1 = (1.f - z1) * n1 + z1 * hold1;
                __half hb1 = __float2half_rn(h1);
                nhh[(size_t)b1o*H + o0 + ol1] = hb1;
                nhl[(size_t)b1o*H + o0 + ol1] = __float2half_rn((h1 - __half2float(hb1)) * 1024.f);
            }
        }

        // two-level tree grid barrier (8 leaves x 8 blocks, acq_rel, monotone)
        __syncthreads();
        if (tid == 0) {
            unsigned tgt = (unsigned)(t + 1);
            unsigned old;
            asm volatile("atom.add.acq_rel.gpu.u32 %0, [%1], 1;"
                         : "=r"(old) : "l"(&g_leaf[leaf*32]) : "memory");
            if (old == tgt*8u - 1u) {
                unsigned rold;
                asm volatile("atom.add.acq_rel.gpu.u32 %0, [%1], 1;"
                             : "=r"(rold) : "l"(&g_root) : "memory");
                if (rold == tgt*8u - 1u) {
                    asm volatile("st.release.gpu.u32 [%0], %1;" :: "l"(&g_gen), "r"(tgt) : "memory");
                }
            }
            unsigned cur;
            do {
                asm volatile("ld.acquire.gpu.u32 %0, [%1];" : "=r"(cur) : "l"(&g_gen) : "memory");
            } while (cur < tgt);
        }
        __syncthreads();
    }
}

// ---------------- final FC + ReLU ----------------
__global__ void fc_kernel(const float* __restrict__ Wfc,
                          const float* __restrict__ bfc,
                          float* __restrict__ out) {
    int idx = blockIdx.x * blockDim.x + threadIdx.x;
    if (idx >= B * NC) return;
    int b = idx / NC, c = idx - b * NC;
    const __half* hh = g_hh[0] + (size_t)b * H;   // T even -> final in buffer 0
    const __half* hl = g_hl[0] + (size_t)b * H;
    float s = bfc[c];
    for (int k = 0; k < H; k += 8) {
        uint4 va = *(const uint4*)(hh + k);
        uint4 vb = *(const uint4*)(hl + k);
        const __half* pa = (const __half*)&va;
        const __half* pb = (const __half*)&vb;
        #pragma unroll
        for (int e = 0; e < 8; ++e) {
            float hv = __half2float(pa[e]) + __half2float(pb[e]) * 9.765625e-4f;
            s += hv * Wfc[(size_t)(k + e) * NC + c];
        }
    }
    out[idx] = fmaxf(s, 0.f);
}

// ---------------- launcher ----------------
extern "C" void kernel_launch(void* const* d_in, const int* in_sizes, int n_in,
                              void* d_out, int out_size) {
    (void)in_sizes; (void)n_in; (void)out_size;
    const float* x    = (const float*)d_in[0];
    const float* c0   = (const float*)d_in[1];
    const float* c1   = (const float*)d_in[2];
    const float* c2   = (const float*)d_in[3];
    const float* c3   = (const float*)d_in[4];
    const float* bi   = (const float*)d_in[5];
    const float* U    = (const float*)d_in[6];
    const float* bh   = (const float*)d_in[7];
    const float* Wfc  = (const float*)d_in[8];
    const float* bfc  = (const float*)d_in[9];

    cudaFuncSetAttribute(ttA_kernel,  cudaFuncAttributeMaxDynamicSharedMemorySize, TTA_SMEM);
    cudaFuncSetAttribute(ttB_kernel,  cudaFuncAttributeMaxDynamicSharedMemorySize, TTB_SMEM);
    cudaFuncSetAttribute(scan_kernel, cudaFuncAttributeMaxDynamicSharedMemorySize, SCAN_SMEM);

    init_kernel<<<64, 256>>>();
    build_M_kernel<<<16, 256>>>(c0, c1, c2, c3);
    build_M34T_kernel<<<24, 256>>>();
    build_UT_kernel<<<dim3(96, 32), dim3(32, 8)>>>(U);
    ttA_kernel<<<BT/16, 256, TTA_SMEM>>>(x);
    ttB_kernel<<<dim3(BT*16/128, 3), 256, TTB_SMEM>>>(bi);
    scan_kernel<<<SCAN_BLOCKS, SCAN_THREADS, SCAN_SMEM>>>(bh);
    fc_kernel<<<(B * NC + 255) / 256, 256>>>(Wfc, bfc, (float*)d_out);
}

// round 15
// speedup vs baseline: 1.3730x; 1.3730x over previous
#include <cuda_runtime.h>
#include <cuda_fp16.h>
#include <cuda_bf16.h>
#include <math.h>
#include <stdint.h>

typedef unsigned long long ull;

// ---------------- problem constants ----------------
#define B   64
#define T   256
#define D   2048
#define H   1024
#define G3  3072
#define NC  1000
#define BT  (B*T)

#define CP_ASYNC16(dst, src) \
    asm volatile("cp.async.cg.shared.global [%0], [%1], 16;" :: "r"(dst), "l"(src))
#define CP_COMMIT() asm volatile("cp.async.commit_group;")
#define CP_WAITN(n) asm volatile("cp.async.wait_group %0;" :: "n"(n))
#define CP_WAIT0()  asm volatile("cp.async.wait_group 0;")

// ---------------- warp MMA helpers ----------------
__device__ __forceinline__ void ldsm_x4(uint32_t* r, unsigned addr) {
    asm volatile("ldmatrix.sync.aligned.m8n8.x4.shared.b16 {%0,%1,%2,%3}, [%4];"
        : "=r"(r[0]), "=r"(r[1]), "=r"(r[2]), "=r"(r[3]) : "r"(addr));
}
__device__ __forceinline__ void ldsm_x2(uint32_t* r, unsigned addr) {
    asm volatile("ldmatrix.sync.aligned.m8n8.x2.shared.b16 {%0,%1}, [%2];"
        : "=r"(r[0]), "=r"(r[1]) : "r"(addr));
}
__device__ __forceinline__ void ldsm_x2t(uint32_t* r, unsigned addr) {
    asm volatile("ldmatrix.sync.aligned.m8n8.x2.trans.shared.b16 {%0,%1}, [%2];"
        : "=r"(r[0]), "=r"(r[1]) : "r"(addr));
}
__device__ __forceinline__ void mma_fp16(float* c, const uint32_t* a, const uint32_t* b) {
    asm volatile(
        "mma.sync.aligned.m16n8k16.row.col.f32.f16.f16.f32 "
        "{%0,%1,%2,%3}, {%4,%5,%6,%7}, {%8,%9}, {%0,%1,%2,%3};"
        : "+f"(c[0]), "+f"(c[1]), "+f"(c[2]), "+f"(c[3])
        : "r"(a[0]), "r"(a[1]), "r"(a[2]), "r"(a[3]), "r"(b[0]), "r"(b[1]));
}

// ---------------- device scratch ----------------
__device__ __align__(16) float  g_M2 [3*2048];                // [g][i1i2(32)][ocr(64)] fp32
__device__ __align__(16) __half g_M2img[192*64];              // swizzled A image [r][128B rows]
__device__ __align__(16) float  g_M34[3*16384];               // [g][k(256)][n(64)] fp32
__device__ __align__(16) __half g_M34h[3*16384];              // [g][n][k] fp16 hi
__device__ __align__(16) __half g_M34l[3*16384];              // [g][n][k] fp16 lo
__device__ __align__(16) __half g_UTf[(size_t)G3*H];          // U^T fp16 [j][k]
__device__ __align__(16) __half g_P  [(size_t)BT*12288];
__device__ __align__(16) float  g_gi [(size_t)BT*G3];         // [t][b][3H]
__device__ __align__(16) __half g_hh[2][B*H];                 // hidden hi fp16 (ping-pong)
__device__ __align__(16) __half g_hl[2][B*H];                 // hidden lo fp16 (x1024), carry only
// tree barrier: 16 leaf counters (128B apart), one root, one generation word
__device__ unsigned g_leaf[16*32];
__device__ unsigned g_root;
__device__ unsigned g_gen;

// ---------------- init ----------------
__global__ void init_kernel() {
    int idx = blockIdx.x * blockDim.x + threadIdx.x;
    unsigned* hh = (unsigned*)g_hh[0];
    unsigned* hl = (unsigned*)g_hl[0];
    for (int i = idx; i < B*H/2; i += gridDim.x * blockDim.x) { hh[i] = 0u; hl[i] = 0u; }
    if (idx < 16*32) g_leaf[idx] = 0u;
    if (idx == 0) { g_root = 0u; g_gen = 0u; }
}

// ---------------- build M2, M34 (grid-parallel) ----------------
__global__ void build_M_kernel(const float* __restrict__ c0,
                               const float* __restrict__ c1,
                               const float* __restrict__ c2,
                               const float* __restrict__ c3) {
    int gid = blockIdx.x * blockDim.x + threadIdx.x;
    int nt  = gridDim.x * blockDim.x;
    for (int idx = gid; idx < 3*2048; idx += nt) {
        int r2 = idx & 3, o2 = (idx>>2)&3, o1 = (idx>>4)&3;
        int i2 = (idx>>6)&7, i1 = (idx>>9)&3, g = idx>>11;
        float s = 0.f;
        #pragma unroll
        for (int r1 = 0; r1 < 4; ++r1)
            s += c0[g*64 + i1*16 + o1*4 + r1] *
                 c1[g*512 + r1*128 + i2*16 + o2*4 + r2];
        g_M2[idx] = s;
    }
    for (int idx = gid; idx < 3*16384; idx += nt) {
        int o4 = idx & 7, o3 = (idx>>3)&7, i4 = (idx>>6)&7;
        int i3 = (idx>>9)&7, r2 = (idx>>12)&3, g = idx>>14;
        float s = 0.f;
        #pragma unroll
        for (int r3 = 0; r3 < 4; ++r3)
            s += c2[g*1024 + r2*256 + i3*32 + o3*4 + r3] *
                 c3[g*256  + r3*64  + i4*8  + o4];
        g_M34[idx] = s;
    }
}

// post-pass: M34 -> [g][n][k] fp16 hi/lo; M2 -> swizzled fp16 A-image
__global__ void build_M34T_kernel() {
    int gid = blockIdx.x * blockDim.x + threadIdx.x;
    int nt  = gridDim.x * blockDim.x;
    for (int idx = gid; idx < 3*16384; idx += nt) {
        int g = idx >> 14, rem = idx & 16383;
        int n = rem >> 8, k = rem & 255;
        float v = g_M34[g*16384 + k*64 + n];
        __half hi = __float2half_rn(v);
        g_M34h[idx] = hi;
        g_M34l[idx] = __float2half_rn(v - __half2float(hi));
    }
    // M2 image: row r (192), k (32): val = M2[g= r>>6][k][ocr = r&63]
    // stored at [r*64 + us*8 + (k&7)] where us = (k>>3) ^ (r&7)
    for (int idx = gid; idx < 192*32; idx += nt) {
        int r = idx >> 5, k = idx & 31;
        float v = g_M2[(r >> 6)*2048 + k*64 + (r & 63)];
        int us = (k >> 3) ^ (r & 7);
        g_M2img[r*64 + us*8 + (k & 7)] = __float2half_rn(v);
    }
}

// ---------------- transpose U [H,G3] -> UT fp16 [G3,H] ----------------
__global__ void build_UT_kernel(const float* __restrict__ U) {
    __shared__ float s[32][33];
    int j0 = blockIdx.x * 32;
    int k0 = blockIdx.y * 32;
    int tx = threadIdx.x, ty = threadIdx.y;
    #pragma unroll
    for (int r = ty; r < 32; r += 8)
        s[r][tx] = U[(size_t)(k0 + r) * G3 + j0 + tx];
    __syncthreads();
    #pragma unroll
    for (int r = ty; r < 32; r += 8)
        g_UTf[(size_t)(j0 + r) * H + k0 + tx] = __float2half_rn(s[tx][r]);
}

// ---------------- TT stage A: HMMA ----------------
// Per bt: P[r(192), q(64)] = M2[r, k32] @ X[k32, q].  Block: 8 warps = 8 bt.
// A = M2 fp16 (swizzled image, cp.async), B = X fp16 via ldmatrix.trans.
#define SC_M2 0                        // 192 rows x 128B = 24576
#define SC_X  24576                    // 8 bt x 4096
#define TTA_SMEM (24576 + 8*4096)      // 57344
__global__ void __launch_bounds__(256)
ttA_kernel(const float* __restrict__ X) {
    extern __shared__ __align__(1024) char smA[];
    const unsigned sb = (unsigned)__cvta_generic_to_shared(smA);
    const int tid = threadIdx.x;
    const int bt0 = blockIdx.x * 8;

    // stage M2 image (pre-swizzled, verbatim copy)
    #pragma unroll
    for (int j = 0; j < 6; ++j) {
        int i = tid + j*256;           // 16B unit 0..1535
        CP_ASYNC16(sb + (unsigned)(i*16), (const char*)g_M2img + i*16);
    }
    CP_COMMIT();

    // stage X fp32 -> fp16, layout S[k][q] rows 128B, swizzled 16B units
    #pragma unroll
    for (int j = 0; j < 16; ++j) {
        int f  = tid + j*256;          // float4 index 0..4095
        int bt = f >> 9;
        int v  = f & 511;
        int k  = v >> 4;
        int q0 = (v & 15) << 2;
        float4 xv = *((const float4*)(X + (size_t)(bt0 + bt)*D) + (k*16 + (v & 15)));
        __half2 h01 = __floats2half2_rn(xv.x, xv.y);
        __half2 h23 = __floats2half2_rn(xv.z, xv.w);
        int us = (q0 >> 3) ^ (k & 7);
        char* dst = smA + SC_X + bt*4096 + k*128 + us*16 + (q0 & 4)*2;
        *(__half2*)(dst)     = h01;
        *(__half2*)(dst + 4) = h23;
    }
    CP_WAIT0();
    __syncthreads();

    const int w    = tid >> 5;
    const int lane = tid & 31;
    const unsigned xbase = sb + (unsigned)SC_X + (unsigned)w*4096u;
    __half* Pb = g_P + (size_t)(bt0 + w) * 12288;

    const int l15 = lane & 15;
    const int l16 = lane >> 4;
    const int lq  = (lane & 3) * 2;   // q offset within n8
    const int lr  = lane >> 2;        // r offset within m16 (0..7)

    for (int rt = 0; rt < 6; ++rt) {
        float c[2][8][4];
        #pragma unroll
        for (int mt = 0; mt < 2; ++mt)
            #pragma unroll
            for (int nt = 0; nt < 8; ++nt)
                #pragma unroll
                for (int e = 0; e < 4; ++e) c[mt][nt][e] = 0.f;

        #pragma unroll
        for (int kh = 0; kh < 2; ++kh) {
            uint32_t a[2][4];
            #pragma unroll
            for (int mt = 0; mt < 2; ++mt) {
                int r = rt*32 + mt*16 + l15;
                int u = kh*2 + l16;
                int us = u ^ (r & 7);
                ldsm_x4(a[mt], sb + (unsigned)(SC_M2 + r*128 + us*16));
            }
            #pragma unroll
            for (int nt = 0; nt < 8; ++nt) {
                uint32_t b[2];
                int k  = kh*16 + l15;
                int us = nt ^ (k & 7);
                ldsm_x2t(b, xbase + (unsigned)(k*128 + us*16));
                mma_fp16(c[0][nt], a[0], b);
                mma_fp16(c[1][nt], a[1], b);
            }
        }

        // epilogue: (c0,c1) = (q,q+1) at r; (c2,c3) at r+8 -> half2 STG
        #pragma unroll
        for (int mt = 0; mt < 2; ++mt) {
            int r0 = rt*32 + mt*16 + lr;
            int r1 = r0 + 8;
            int off0 = ((r0 >> 6)*16 + ((r0 >> 2) & 15))*256 + (r0 & 3)*64;
            int off1 = ((r1 >> 6)*16 + ((r1 >> 2) & 15))*256 + (r1 & 3)*64;
            #pragma unroll
            for (int nt = 0; nt < 8; ++nt) {
                int q = nt*8 + lq;
                *(__half2*)(Pb + off0 + q) = __floats2half2_rn(c[mt][nt][0], c[mt][nt][1]);
                *(__half2*)(Pb + off1 + q) = __floats2half2_rn(c[mt][nt][2], c[mt][nt][3]);
            }
        }
    }
}

// ---------------- TT stage B: HMMA (unchanged) ----------------
#define TTB_SMEM (65536 + 32768 + 32768)   // A 64KB | Bh 32KB | Bl 32KB
__global__ void __launch_bounds__(256)
ttB_kernel(const float* __restrict__ bi) {
    extern __shared__ __align__(1024) char smB[];
    const unsigned sb = (unsigned)__cvta_generic_to_shared(smB);
    const int tid = threadIdx.x;
    const int g   = blockIdx.y;
    const int m0  = blockIdx.x * 128;

    for (int i = tid; i < 4096; i += 256) {
        int r = i >> 5, u = i & 31;
        int us = (u & ~7) | ((u & 7) ^ (r & 7));
        int m = m0 + r;
        const __half* src = g_P + ((size_t)(m >> 4)*48 + g*16 + (m & 15))*256 + u*8;
        CP_ASYNC16(sb + (unsigned)(r*512 + us*16), src);
    }
    for (int i = tid; i < 2048; i += 256) {
        int n = i >> 5, u = i & 31;
        int us = (u & ~7) | ((u & 7) ^ (n & 7));
        const __half* s1 = g_M34h + ((size_t)g*64 + n)*256 + u*8;
        const __half* s2 = g_M34l + ((size_t)g*64 + n)*256 + u*8;
        CP_ASYNC16(sb + 65536u + (unsigned)(n*512 + us*16), s1);
        CP_ASYNC16(sb + 98304u + (unsigned)(n*512 + us*16), s2);
    }
    CP_COMMIT(); CP_WAIT0();
    __syncthreads();

    const int wid = tid >> 5, lane = tid & 31;
    const int wm = wid & 3, wn = wid >> 2;
    const int lrow = lane & 15, lk = lane >> 4;

    float c[2][4][4];
    #pragma unroll
    for (int ms = 0; ms < 2; ++ms)
        #pragma unroll
        for (int j = 0; j < 4; ++j)
            #pragma unroll
            for (int e = 0; e < 4; ++e) c[ms][j][e] = 0.f;

    #pragma unroll
    for (int ks = 0; ks < 16; ++ks) {
        const int u = ks*2 + lk;
        uint32_t a[2][4], bh4[2][4], bl4[2][4];
        #pragma unroll
        for (int ms = 0; ms < 2; ++ms) {
            int r = wm*32 + ms*16 + lrow;
            int us = (u & ~7) | ((u & 7) ^ (r & 7));
            ldsm_x4(a[ms], sb + (unsigned)(r*512 + us*16));
        }
        #pragma unroll
        for (int ns = 0; ns < 2; ++ns) {
            int n = wn*32 + ns*16 + lrow;
            int us = (u & ~7) | ((u & 7) ^ (n & 7));
            ldsm_x4(bh4[ns], sb + 65536u + (unsigned)(n*512 + us*16));
            ldsm_x4(bl4[ns], sb + 98304u + (unsigned)(n*512 + us*16));
        }
        #pragma unroll
        for (int ms = 0; ms < 2; ++ms)
            #pragma unroll
            for (int j = 0; j < 4; ++j) {
                uint32_t bfh[2] = { bh4[j>>1][j&1], bh4[j>>1][(j&1)+2] };
                uint32_t bfl[2] = { bl4[j>>1][j&1], bl4[j>>1][(j&1)+2] };
                mma_fp16(c[ms][j], a[ms], bfh);
                mma_fp16(c[ms][j], a[ms], bfl);
            }
    }

    #pragma unroll
    for (int ms = 0; ms < 2; ++ms) {
        #pragma unroll
        for (int j = 0; j < 4; ++j) {
            int nn = wn*32 + j*8 + (lane & 3)*2;
            #pragma unroll
            for (int half = 0; half < 2; ++half) {
                int r = wm*32 + ms*16 + (lane >> 2) + half*8;
                int m = m0 + r;
                int bt = m >> 4, oo = m & 15;
                int bb = bt >> 8, tt = bt & 255;
                const float* bp = bi + g*1024 + oo*64 + nn;
                float2 v;
                v.x = c[ms][j][half*2]     + bp[0];
                v.y = c[ms][j][half*2 + 1] + bp[1];
                *(float2*)(g_gi + ((size_t)tt*B + bb)*G3 + g*1024 + oo*64 + nn) = v;
            }
        }
    }
}

// ---------------- persistent mma.sync scan (R13 config, reverted) ----------------
// 128 blocks x 384 thr (12 warps = 4 M x 3 gates).
// h MMA operand: single fp16 (hi). Carry stays fp16 hi+lo in global.
// All 4 K-chunks staged up-front per step (4 commit groups).
#define SCAN_BLOCKS 128
#define SCAN_THREADS 384
#define SC_B  0                      // 24 x 2048B (U fp16, swizzled)
#define SC_A  49152                  // 4 chunks x 32768
#define SCAN_SMEM (49152 + 131072)   // 180224

__device__ __forceinline__ void stageA_chunk(const __half* hh, unsigned sb, int ck, int tid) {
    const unsigned base = sb + (unsigned)SC_A + (unsigned)ck*32768u;
    for (int i = tid; i < 2048; i += SCAN_THREADS) {
        int b = i >> 5, u = i & 31;
        int us = (u & ~7) | ((u & 7) ^ (b & 7));
        CP_ASYNC16(base + (unsigned)(b*512 + us*16), hh + (size_t)b*H + ck*256 + u*8);
    }
    CP_COMMIT();
}

__global__ void __launch_bounds__(SCAN_THREADS, 1)
scan_kernel(const float* __restrict__ bh) {
    extern __shared__ __align__(1024) char smem[];
    const unsigned sb = (unsigned)__cvta_generic_to_shared(smem);
    const int tid  = threadIdx.x;
    const int wid  = tid >> 5;
    const int lane = tid & 31;
    const int o0   = blockIdx.x * 8;
    const int wm   = wid & 3;            // M-tile (batches wm*16..+15)
    const int wg   = wid >> 2;           // gate / N-tile (0..2)
    const int leaf = blockIdx.x >> 3;    // 16 leaves of 8 blocks

    // stage B = UT slice fp16 (rows n = g*8+ol), swizzled for ldmatrix
    for (int i = tid; i < 3072; i += SCAN_THREADS) {
        int n = i >> 7, u = i & 127;
        int us = (u & ~7) | ((u & 7) ^ (n & 7));
        int g = n >> 3, ol = n & 7;
        size_t src = ((size_t)(g*H + o0 + ol))*H + (size_t)u*8;
        *(uint4*)(smem + SC_B + n*2048 + us*16) = *(const uint4*)(g_UTf + src);
    }
    __syncthreads();

    const int arow   = wm*16 + (lane & 15);
    const int kadd8  = lane >> 4;
    const unsigned arow_off = (unsigned)(arow * 512);
    const int arow7  = arow & 7;
    const int brow   = wg*8 + (lane & 7);
    const unsigned brow_off = (unsigned)(brow * 2048);
    const int brow7  = brow & 7;
    const int bk8    = (lane >> 3) & 1;

    const int b0o = tid >> 3,         ol0 = tid & 7;
    const int b1o = (tid + 384) >> 3, ol1 = tid & 7;
    float bh0v[3], bh1v[3];
    #pragma unroll
    for (int g = 0; g < 3; ++g) {
        bh0v[g] = bh[g*H + o0 + ol0];
        bh1v[g] = bh[g*H + o0 + ol1];
    }

    float* red = (float*)(smem + SC_A);       // [3][64][8] fp32, aliases A chunk 0

    for (int t = 0; t < T; ++t) {
        const __half* hh = g_hh[t & 1];
        const __half* hl = g_hl[t & 1];
        __half* nhh = g_hh[(t & 1) ^ 1];
        __half* nhl = g_hl[(t & 1) ^ 1];

        // stage ALL 4 chunks (4 async groups)
        stageA_chunk(hh, sb, 0, tid);
        stageA_chunk(hh, sb, 1, tid);
        stageA_chunk(hh, sb, 2, tid);
        stageA_chunk(hh, sb, 3, tid);

        float gi0[3], gi1[3], hold0, hold1;
        {
            const float* gp0 = g_gi + ((size_t)t*B + b0o)*G3 + o0 + ol0;
            #pragma unroll
            for (int g = 0; g < 3; ++g) gi0[g] = __ldg(gp0 + g*H);
            hold0 = __half2float(hh[(size_t)b0o*H + o0 + ol0])
                  + __half2float(hl[(size_t)b0o*H + o0 + ol0]) * 9.765625e-4f;
            if (tid < 128) {
                const float* gp1 = g_gi + ((size_t)t*B + b1o)*G3 + o0 + ol1;
                #pragma unroll
                for (int g = 0; g < 3; ++g) gi1[g] = __ldg(gp1 + g*H);
                hold1 = __half2float(hh[(size_t)b1o*H + o0 + ol1])
                      + __half2float(hl[(size_t)b1o*H + o0 + ol1]) * 9.765625e-4f;
            }
        }

        float c[4] = {0.f, 0.f, 0.f, 0.f};

        #define SCAN_CHUNK(CK, PEND)                                           \
        {                                                                      \
            CP_WAITN(PEND);                                                    \
            __syncthreads();                                                   \
            const unsigned aB = sb + (unsigned)SC_A + (unsigned)(CK*32768);    \
            _Pragma("unroll")                                                  \
            for (int ks = 0; ks < 16; ++ks) {                                  \
                uint32_t ah[4], br[2];                                         \
                int u  = ks*2 + kadd8;                                         \
                int us = (u & ~7) | ((u & 7) ^ arow7);                         \
                ldsm_x4(ah, aB + arow_off + (unsigned)(us*16));                \
                int kg  = CK*32 + ks*2 + bk8;                                  \
                int bus = (kg & ~7) | ((kg & 7) ^ brow7);                      \
                ldsm_x2(br, sb + (unsigned)SC_B + brow_off + (unsigned)(bus*16)); \
                mma_fp16(c, ah, br);                                           \
            }                                                                  \
        }
        SCAN_CHUNK(0, 3)
        SCAN_CHUNK(1, 2)
        SCAN_CHUNK(2, 1)
        SCAN_CHUNK(3, 0)
        #undef SCAN_CHUNK

        // scatter C frags to red[g][b][ol]  (red aliases chunk 0; all reads done)
        __syncthreads();
        {
            int row = wm*16 + (lane >> 2);
            int col = (lane & 3) * 2;
            float* rg = red + wg*512;
            rg[row*8 + col]         = c[0];
            rg[row*8 + col + 1]     = c[1];
            rg[(row+8)*8 + col]     = c[2];
            rg[(row+8)*8 + col + 1] = c[3];
        }
        __syncthreads();

        // pointwise GRU update
        {
            float s0 = red[        b0o*8 + ol0];
            float s1 = red[ 512 +  b0o*8 + ol0];
            float s2 = red[1024 +  b0o*8 + ol0];
            float r  = 1.f / (1.f + __expf(-(gi0[0] + s0 + bh0v[0])));
            float z  = 1.f / (1.f + __expf(-(gi0[1] + s1 + bh0v[1])));
            float na = gi0[2] + r * (s2 + bh0v[2]);
            float te = __expf(2.f * na);
            float n  = 1.f - 2.f / (te + 1.f);
            float hn = (1.f - z) * n + z * hold0;
            __half hb = __float2half_rn(hn);
            nhh[(size_t)b0o*H + o0 + ol0] = hb;
            nhl[(size_t)b0o*H + o0 + ol0] = __float2half_rn((hn - __half2float(hb)) * 1024.f);
            if (tid < 128) {
                float q0 = red[        b1o*8 + ol1];
                float q1 = red[ 512 +  b1o*8 + ol1];
                float q2 = red[1024 +  b1o*8 + ol1];
                float r1 = 1.f / (1.f + __expf(-(gi1[0] + q0 + bh1v[0])));
                float z1 = 1.f / (1.f + __expf(-(gi1[1] + q1 + bh1v[1])));
                float nb = gi1[2] + r1 * (q2 + bh1v[2]);
                float t2 = __expf(2.f * nb);
                float n1 = 1.f - 2.f / (t2 + 1.f);
                float h1 = (1.f - z1) * n1 + z1 * hold1;
                __half hb1 = __float2half_rn(h1);
                nhh[(size_t)b1o*H + o0 + ol1] = hb1;
                nhl[(size_t)b1o*H + o0 + ol1] = __float2half_rn((h1 - __half2float(hb1)) * 1024.f);
            }
        }

        // two-level tree grid barrier (acq_rel, monotone counters)
        __syncthreads();
        if (tid == 0) {
            unsigned tgt = (unsigned)(t + 1);
            unsigned old;
            asm volatile("atom.add.acq_rel.gpu.u32 %0, [%1], 1;"
                         : "=r"(old) : "l"(&g_leaf[leaf*32]) : "memory");
            if (old == tgt*8u - 1u) {
                unsigned rold;
                asm volatile("atom.add.acq_rel.gpu.u32 %0, [%1], 1;"
                             : "=r"(rold) : "l"(&g_root) : "memory");
                if (rold == tgt*16u - 1u) {
                    asm volatile("st.release.gpu.u32 [%0], %1;" :: "l"(&g_gen), "r"(tgt) : "memory");
                }
            }
            unsigned cur;
            do {
                asm volatile("ld.acquire.gpu.u32 %0, [%1];" : "=r"(cur) : "l"(&g_gen) : "memory");
            } while (cur < tgt);
        }
        __syncthreads();
    }
}

// ---------------- final FC + ReLU ----------------
__global__ void fc_kernel(const float* __restrict__ Wfc,
                          const float* __restrict__ bfc,
                          float* __restrict__ out) {
    int idx = blockIdx.x * blockDim.x + threadIdx.x;
    if (idx >= B * NC) return;
    int b = idx / NC, c = idx - b * NC;
    const __half* hh = g_hh[0] + (size_t)b * H;   // T even -> final in buffer 0
    const __half* hl = g_hl[0] + (size_t)b * H;
    float s = bfc[c];
    for (int k = 0; k < H; k += 8) {
        uint4 va = *(const uint4*)(hh + k);
        uint4 vb = *(const uint4*)(hl + k);
        const __half* pa = (const __half*)&va;
        const __half* pb = (const __half*)&vb;
        #pragma unroll
        for (int e = 0; e < 8; ++e) {
            float hv = __half2float(pa[e]) + __half2float(pb[e]) * 9.765625e-4f;
            s += hv * Wfc[(size_t)(k + e) * NC + c];
        }
    }
    out[idx] = fmaxf(s, 0.f);
}

// ---------------- launcher ----------------
extern "C" void kernel_launch(void* const* d_in, const int* in_sizes, int n_in,
                              void* d_out, int out_size) {
    (void)in_sizes; (void)n_in; (void)out_size;
    const float* x    = (const float*)d_in[0];
    const float* c0   = (const float*)d_in[1];
    const float* c1   = (const float*)d_in[2];
    const float* c2   = (const float*)d_in[3];
    const float* c3   = (const float*)d_in[4];
    const float* bi   = (const float*)d_in[5];
    const float* U    = (const float*)d_in[6];
    const float* bh   = (const float*)d_in[7];
    const float* Wfc  = (const float*)d_in[8];
    const float* bfc  = (const float*)d_in[9];

    cudaFuncSetAttribute(ttA_kernel,  cudaFuncAttributeMaxDynamicSharedMemorySize, TTA_SMEM);
    cudaFuncSetAttribute(ttB_kernel,  cudaFuncAttributeMaxDynamicSharedMemorySize, TTB_SMEM);
    cudaFuncSetAttribute(scan_kernel, cudaFuncAttributeMaxDynamicSharedMemorySize, SCAN_SMEM);

    init_kernel<<<64, 256>>>();
    build_M_kernel<<<16, 256>>>(c0, c1, c2, c3);
    build_M34T_kernel<<<24, 256>>>();
    build_UT_kernel<<<dim3(96, 32), dim3(32, 8)>>>(U);
    ttA_kernel<<<BT/8, 256, TTA_SMEM>>>(x);
    ttB_kernel<<<dim3(BT*16/128, 3), 256, TTB_SMEM>>>(bi);
    scan_kernel<<<SCAN_BLOCKS, SCAN_THREADS, SCAN_SMEM>>>(bh);
    fc_kernel<<<(B * NC + 255) / 256, 256>>>(Wfc, bfc, (float*)d_out);
}

// round 16
// speedup vs baseline: 1.6805x; 1.2239x over previous
#include <cuda_runtime.h>
#include <cuda_fp16.h>
#include <cuda_bf16.h>
#include <math.h>
#include <stdint.h>

typedef unsigned long long ull;

// ---------------- problem constants ----------------
#define B   64
#define T   256
#define D   2048
#define H   1024
#define G3  3072
#define NC  1000
#define BT  (B*T)

#define CP_ASYNC16(dst, src) \
    asm volatile("cp.async.cg.shared.global [%0], [%1], 16;" :: "r"(dst), "l"(src))
#define CP_COMMIT() asm volatile("cp.async.commit_group;")
#define CP_WAITN(n) asm volatile("cp.async.wait_group %0;" :: "n"(n))
#define CP_WAIT0()  asm volatile("cp.async.wait_group 0;")

// ---------------- warp MMA helpers ----------------
__device__ __forceinline__ void ldsm_x4(uint32_t* r, unsigned addr) {
    asm volatile("ldmatrix.sync.aligned.m8n8.x4.shared.b16 {%0,%1,%2,%3}, [%4];"
        : "=r"(r[0]), "=r"(r[1]), "=r"(r[2]), "=r"(r[3]) : "r"(addr));
}
__device__ __forceinline__ void ldsm_x2(uint32_t* r, unsigned addr) {
    asm volatile("ldmatrix.sync.aligned.m8n8.x2.shared.b16 {%0,%1}, [%2];"
        : "=r"(r[0]), "=r"(r[1]) : "r"(addr));
}
__device__ __forceinline__ void ldsm_x2t(uint32_t* r, unsigned addr) {
    asm volatile("ldmatrix.sync.aligned.m8n8.x2.trans.shared.b16 {%0,%1}, [%2];"
        : "=r"(r[0]), "=r"(r[1]) : "r"(addr));
}
__device__ __forceinline__ void mma_fp16(float* c, const uint32_t* a, const uint32_t* b) {
    asm volatile(
        "mma.sync.aligned.m16n8k16.row.col.f32.f16.f16.f32 "
        "{%0,%1,%2,%3}, {%4,%5,%6,%7}, {%8,%9}, {%0,%1,%2,%3};"
        : "+f"(c[0]), "+f"(c[1]), "+f"(c[2]), "+f"(c[3])
        : "r"(a[0]), "r"(a[1]), "r"(a[2]), "r"(a[3]), "r"(b[0]), "r"(b[1]));
}

// ---------------- device scratch ----------------
__device__ __align__(16) float  g_M2 [3*2048];                // [g][i1i2(32)][ocr(64)] fp32
__device__ __align__(16) __half g_M2img[192*64];              // swizzled A image [r][128B rows]
__device__ __align__(16) float  g_M34[3*16384];               // [g][k(256)][n(64)] fp32
__device__ __align__(16) __half g_M34h[3*16384];              // [g][n][k] fp16 hi
__device__ __align__(16) __half g_M34l[3*16384];              // [g][n][k] fp16 lo
__device__ __align__(16) __half g_UTf[(size_t)G3*H];          // U^T fp16 [j][k]
__device__ __align__(16) __half g_P  [(size_t)BT*12288];
__device__ __align__(16) float  g_gi [(size_t)BT*G3];         // [t][b][3H]
__device__ __align__(16) __half g_hh[2][B*H];                 // hidden hi fp16 (ping-pong)
__device__ __align__(16) __half g_hl[2][B*H];                 // hidden lo fp16 (x1024), carry only
// tree barrier: 16 leaf counters (128B apart), one root, one generation word
__device__ unsigned g_leaf[16*32];
__device__ unsigned g_root;
__device__ unsigned g_gen;

// ---------------- init ----------------
__global__ void init_kernel() {
    int idx = blockIdx.x * blockDim.x + threadIdx.x;
    unsigned* hh = (unsigned*)g_hh[0];
    unsigned* hl = (unsigned*)g_hl[0];
    for (int i = idx; i < B*H/2; i += gridDim.x * blockDim.x) { hh[i] = 0u; hl[i] = 0u; }
    if (idx < 16*32) g_leaf[idx] = 0u;
    if (idx == 0) { g_root = 0u; g_gen = 0u; }
}

// ---------------- build M2, M34 (grid-parallel) ----------------
__global__ void build_M_kernel(const float* __restrict__ c0,
                               const float* __restrict__ c1,
                               const float* __restrict__ c2,
                               const float* __restrict__ c3) {
    int gid = blockIdx.x * blockDim.x + threadIdx.x;
    int nt  = gridDim.x * blockDim.x;
    for (int idx = gid; idx < 3*2048; idx += nt) {
        int r2 = idx & 3, o2 = (idx>>2)&3, o1 = (idx>>4)&3;
        int i2 = (idx>>6)&7, i1 = (idx>>9)&3, g = idx>>11;
        float s = 0.f;
        #pragma unroll
        for (int r1 = 0; r1 < 4; ++r1)
            s += c0[g*64 + i1*16 + o1*4 + r1] *
                 c1[g*512 + r1*128 + i2*16 + o2*4 + r2];
        g_M2[idx] = s;
    }
    for (int idx = gid; idx < 3*16384; idx += nt) {
        int o4 = idx & 7, o3 = (idx>>3)&7, i4 = (idx>>6)&7;
        int i3 = (idx>>9)&7, r2 = (idx>>12)&3, g = idx>>14;
        float s = 0.f;
        #pragma unroll
        for (int r3 = 0; r3 < 4; ++r3)
            s += c2[g*1024 + r2*256 + i3*32 + o3*4 + r3] *
                 c3[g*256  + r3*64  + i4*8  + o4];
        g_M34[idx] = s;
    }
}

// post-pass: M34 -> [g][n][k] fp16 hi/lo; M2 -> swizzled fp16 A-image
__global__ void build_M34T_kernel() {
    int gid = blockIdx.x * blockDim.x + threadIdx.x;
    int nt  = gridDim.x * blockDim.x;
    for (int idx = gid; idx < 3*16384; idx += nt) {
        int g = idx >> 14, rem = idx & 16383;
        int n = rem >> 8, k = rem & 255;
        float v = g_M34[g*16384 + k*64 + n];
        __half hi = __float2half_rn(v);
        g_M34h[idx] = hi;
        g_M34l[idx] = __float2half_rn(v - __half2float(hi));
    }
    for (int idx = gid; idx < 192*32; idx += nt) {
        int r = idx >> 5, k = idx & 31;
        float v = g_M2[(r >> 6)*2048 + k*64 + (r & 63)];
        int us = (k >> 3) ^ (r & 7);
        g_M2img[r*64 + us*8 + (k & 7)] = __float2half_rn(v);
    }
}

// ---------------- transpose U [H,G3] -> UT fp16 [G3,H] ----------------
__global__ void build_UT_kernel(const float* __restrict__ U) {
    __shared__ float s[32][33];
    int j0 = blockIdx.x * 32;
    int k0 = blockIdx.y * 32;
    int tx = threadIdx.x, ty = threadIdx.y;
    #pragma unroll
    for (int r = ty; r < 32; r += 8)
        s[r][tx] = U[(size_t)(k0 + r) * G3 + j0 + tx];
    __syncthreads();
    #pragma unroll
    for (int r = ty; r < 32; r += 8)
        g_UTf[(size_t)(j0 + r) * H + k0 + tx] = __float2half_rn(s[tx][r]);
}

// ---------------- TT stage A: HMMA ----------------
#define SC_M2 0                        // 192 rows x 128B = 24576
#define SC_X  24576                    // 8 bt x 4096
#define TTA_SMEM (24576 + 8*4096)      // 57344
__global__ void __launch_bounds__(256)
ttA_kernel(const float* __restrict__ X) {
    extern __shared__ __align__(1024) char smA[];
    const unsigned sb = (unsigned)__cvta_generic_to_shared(smA);
    const int tid = threadIdx.x;
    const int bt0 = blockIdx.x * 8;

    #pragma unroll
    for (int j = 0; j < 6; ++j) {
        int i = tid + j*256;
        CP_ASYNC16(sb + (unsigned)(i*16), (const char*)g_M2img + i*16);
    }
    CP_COMMIT();

    #pragma unroll
    for (int j = 0; j < 16; ++j) {
        int f  = tid + j*256;
        int bt = f >> 9;
        int v  = f & 511;
        int k  = v >> 4;
        int q0 = (v & 15) << 2;
        float4 xv = *((const float4*)(X + (size_t)(bt0 + bt)*D) + (k*16 + (v & 15)));
        __half2 h01 = __floats2half2_rn(xv.x, xv.y);
        __half2 h23 = __floats2half2_rn(xv.z, xv.w);
        int us = (q0 >> 3) ^ (k & 7);
        char* dst = smA + SC_X + bt*4096 + k*128 + us*16 + (q0 & 4)*2;
        *(__half2*)(dst)     = h01;
        *(__half2*)(dst + 4) = h23;
    }
    CP_WAIT0();
    __syncthreads();

    const int w    = tid >> 5;
    const int lane = tid & 31;
    const unsigned xbase = sb + (unsigned)SC_X + (unsigned)w*4096u;
    __half* Pb = g_P + (size_t)(bt0 + w) * 12288;

    const int l15 = lane & 15;
    const int l16 = lane >> 4;
    const int lq  = (lane & 3) * 2;
    const int lr  = lane >> 2;

    for (int rt = 0; rt < 6; ++rt) {
        float c[2][8][4];
        #pragma unroll
        for (int mt = 0; mt < 2; ++mt)
            #pragma unroll
            for (int nt = 0; nt < 8; ++nt)
                #pragma unroll
                for (int e = 0; e < 4; ++e) c[mt][nt][e] = 0.f;

        #pragma unroll
        for (int kh = 0; kh < 2; ++kh) {
            uint32_t a[2][4];
            #pragma unroll
            for (int mt = 0; mt < 2; ++mt) {
                int r = rt*32 + mt*16 + l15;
                int u = kh*2 + l16;
                int us = u ^ (r & 7);
                ldsm_x4(a[mt], sb + (unsigned)(SC_M2 + r*128 + us*16));
            }
            #pragma unroll
            for (int nt = 0; nt < 8; ++nt) {
                uint32_t b[2];
                int k  = kh*16 + l15;
                int us = nt ^ (k & 7);
                ldsm_x2t(b, xbase + (unsigned)(k*128 + us*16));
                mma_fp16(c[0][nt], a[0], b);
                mma_fp16(c[1][nt], a[1], b);
            }
        }

        #pragma unroll
        for (int mt = 0; mt < 2; ++mt) {
            int r0 = rt*32 + mt*16 + lr;
            int r1 = r0 + 8;
            int off0 = ((r0 >> 6)*16 + ((r0 >> 2) & 15))*256 + (r0 & 3)*64;
            int off1 = ((r1 >> 6)*16 + ((r1 >> 2) & 15))*256 + (r1 & 3)*64;
            #pragma unroll
            for (int nt = 0; nt < 8; ++nt) {
                int q = nt*8 + lq;
                *(__half2*)(Pb + off0 + q) = __floats2half2_rn(c[mt][nt][0], c[mt][nt][1]);
                *(__half2*)(Pb + off1 + q) = __floats2half2_rn(c[mt][nt][2], c[mt][nt][3]);
            }
        }
    }
}

// ---------------- TT stage B: HMMA (unchanged) ----------------
#define TTB_SMEM (65536 + 32768 + 32768)   // A 64KB | Bh 32KB | Bl 32KB
__global__ void __launch_bounds__(256)
ttB_kernel(const float* __restrict__ bi) {
    extern __shared__ __align__(1024) char smB[];
    const unsigned sb = (unsigned)__cvta_generic_to_shared(smB);
    const int tid = threadIdx.x;
    const int g   = blockIdx.y;
    const int m0  = blockIdx.x * 128;

    for (int i = tid; i < 4096; i += 256) {
        int r = i >> 5, u = i & 31;
        int us = (u & ~7) | ((u & 7) ^ (r & 7));
        int m = m0 + r;
        const __half* src = g_P + ((size_t)(m >> 4)*48 + g*16 + (m & 15))*256 + u*8;
        CP_ASYNC16(sb + (unsigned)(r*512 + us*16), src);
    }
    for (int i = tid; i < 2048; i += 256) {
        int n = i >> 5, u = i & 31;
        int us = (u & ~7) | ((u & 7) ^ (n & 7));
        const __half* s1 = g_M34h + ((size_t)g*64 + n)*256 + u*8;
        const __half* s2 = g_M34l + ((size_t)g*64 + n)*256 + u*8;
        CP_ASYNC16(sb + 65536u + (unsigned)(n*512 + us*16), s1);
        CP_ASYNC16(sb + 98304u + (unsigned)(n*512 + us*16), s2);
    }
    CP_COMMIT(); CP_WAIT0();
    __syncthreads();

    const int wid = tid >> 5, lane = tid & 31;
    const int wm = wid & 3, wn = wid >> 2;
    const int lrow = lane & 15, lk = lane >> 4;

    float c[2][4][4];
    #pragma unroll
    for (int ms = 0; ms < 2; ++ms)
        #pragma unroll
        for (int j = 0; j < 4; ++j)
            #pragma unroll
            for (int e = 0; e < 4; ++e) c[ms][j][e] = 0.f;

    #pragma unroll
    for (int ks = 0; ks < 16; ++ks) {
        const int u = ks*2 + lk;
        uint32_t a[2][4], bh4[2][4], bl4[2][4];
        #pragma unroll
        for (int ms = 0; ms < 2; ++ms) {
            int r = wm*32 + ms*16 + lrow;
            int us = (u & ~7) | ((u & 7) ^ (r & 7));
            ldsm_x4(a[ms], sb + (unsigned)(r*512 + us*16));
        }
        #pragma unroll
        for (int ns = 0; ns < 2; ++ns) {
            int n = wn*32 + ns*16 + lrow;
            int us = (u & ~7) | ((u & 7) ^ (n & 7));
            ldsm_x4(bh4[ns], sb + 65536u + (unsigned)(n*512 + us*16));
            ldsm_x4(bl4[ns], sb + 98304u + (unsigned)(n*512 + us*16));
        }
        #pragma unroll
        for (int ms = 0; ms < 2; ++ms)
            #pragma unroll
            for (int j = 0; j < 4; ++j) {
                uint32_t bfh[2] = { bh4[j>>1][j&1], bh4[j>>1][(j&1)+2] };
                uint32_t bfl[2] = { bl4[j>>1][j&1], bl4[j>>1][(j&1)+2] };
                mma_fp16(c[ms][j], a[ms], bfh);
                mma_fp16(c[ms][j], a[ms], bfl);
            }
    }

    #pragma unroll
    for (int ms = 0; ms < 2; ++ms) {
        #pragma unroll
        for (int j = 0; j < 4; ++j) {
            int nn = wn*32 + j*8 + (lane & 3)*2;
            #pragma unroll
            for (int half = 0; half < 2; ++half) {
                int r = wm*32 + ms*16 + (lane >> 2) + half*8;
                int m = m0 + r;
                int bt = m >> 4, oo = m & 15;
                int bb = bt >> 8, tt = bt & 255;
                const float* bp = bi + g*1024 + oo*64 + nn;
                float2 v;
                v.x = c[ms][j][half*2]     + bp[0];
                v.y = c[ms][j][half*2 + 1] + bp[1];
                *(float2*)(g_gi + ((size_t)tt*B + bb)*G3 + g*1024 + oo*64 + nn) = v;
            }
        }
    }
}

// ---------------- persistent mma.sync scan v2 ----------------
// 128 blocks x 512 thr: 16 warps = 4 M-tiles x 4 k-quarters.
// Each warp computes ALL 3 gates for its (M, kq): 1 A-load feeds 3 MMAs.
// Cross-warp k-reduction over 4 partials via smem red buffer.
#define SCAN_BLOCKS 128
#define SCAN_THREADS 512
#define SC_B  0                      // 24 x 2048B (U fp16, swizzled)
#define SC_A  49152                  // 4 chunks x 32768
#define SCAN_SMEM (49152 + 131072)   // 180224

__device__ __forceinline__ void stageA_chunk(const __half* hh, unsigned sb, int ck, int tid) {
    const unsigned base = sb + (unsigned)SC_A + (unsigned)ck*32768u;
    for (int i = tid; i < 2048; i += SCAN_THREADS) {
        int b = i >> 5, u = i & 31;
        int us = (u & ~7) | ((u & 7) ^ (b & 7));
        CP_ASYNC16(base + (unsigned)(b*512 + us*16), hh + (size_t)b*H + ck*256 + u*8);
    }
    CP_COMMIT();
}

__global__ void __launch_bounds__(SCAN_THREADS, 1)
scan_kernel(const float* __restrict__ bh) {
    extern __shared__ __align__(1024) char smem[];
    const unsigned sb = (unsigned)__cvta_generic_to_shared(smem);
    const int tid  = threadIdx.x;
    const int wid  = tid >> 5;
    const int lane = tid & 31;
    const int o0   = blockIdx.x * 8;
    const int wm   = wid & 3;            // M-tile (batches wm*16..+15)
    const int wq   = wid >> 2;           // k-quarter (0..3)
    const int leaf = blockIdx.x >> 3;    // 16 leaves of 8 blocks

    // stage B = UT slice fp16 (rows n = g*8+ol), swizzled for ldmatrix
    for (int i = tid; i < 3072; i += SCAN_THREADS) {
        int n = i >> 7, u = i & 127;
        int us = (u & ~7) | ((u & 7) ^ (n & 7));
        int g = n >> 3, ol = n & 7;
        size_t src = ((size_t)(g*H + o0 + ol))*H + (size_t)u*8;
        *(uint4*)(smem + SC_B + n*2048 + us*16) = *(const uint4*)(g_UTf + src);
    }
    __syncthreads();

    const int arow   = wm*16 + (lane & 15);
    const int kadd8  = lane >> 4;
    const unsigned arow_off = (unsigned)(arow * 512);
    const int arow7  = arow & 7;
    const int l7     = lane & 7;
    const int bk8    = (lane >> 3) & 1;

    // pointwise: exactly one output per thread
    const int b0o = tid >> 3, ol0 = tid & 7;
    float bh0v[3];
    #pragma unroll
    for (int g = 0; g < 3; ++g) bh0v[g] = bh[g*H + o0 + ol0];

    float* red = (float*)(smem + SC_A);       // [4 kq][3 g][64 b][8 o], aliases A chunk 0

    for (int t = 0; t < T; ++t) {
        const __half* hh = g_hh[t & 1];
        const __half* hl = g_hl[t & 1];
        __half* nhh = g_hh[(t & 1) ^ 1];
        __half* nhl = g_hl[(t & 1) ^ 1];

        // stage ALL 4 chunks (4 async groups)
        stageA_chunk(hh, sb, 0, tid);
        stageA_chunk(hh, sb, 1, tid);
        stageA_chunk(hh, sb, 2, tid);
        stageA_chunk(hh, sb, 3, tid);

        float gi0[3], hold0;
        {
            const float* gp0 = g_gi + ((size_t)t*B + b0o)*G3 + o0 + ol0;
            #pragma unroll
            for (int g = 0; g < 3; ++g) gi0[g] = __ldg(gp0 + g*H);
            hold0 = __half2float(hh[(size_t)b0o*H + o0 + ol0])
                  + __half2float(hl[(size_t)b0o*H + o0 + ol0]) * 9.765625e-4f;
        }

        float c[3][4];
        #pragma unroll
        for (int g = 0; g < 3; ++g)
            #pragma unroll
            for (int e = 0; e < 4; ++e) c[g][e] = 0.f;

        #define SCAN_CHUNK(CK, PEND)                                             \
        {                                                                        \
            CP_WAITN(PEND);                                                      \
            __syncthreads();                                                     \
            const unsigned aB = sb + (unsigned)SC_A + (unsigned)(CK*32768);      \
            _Pragma("unroll")                                                    \
            for (int j = 0; j < 4; ++j) {                                        \
                int ks = wq*4 + j;                                               \
                uint32_t ah[4], br[2];                                           \
                int u  = ks*2 + kadd8;                                           \
                int us = (u & ~7) | ((u & 7) ^ arow7);                           \
                ldsm_x4(ah, aB + arow_off + (unsigned)(us*16));                  \
                int kg  = CK*32 + ks*2 + bk8;                                    \
                int bus = (kg & ~7) | ((kg & 7) ^ l7);                           \
                _Pragma("unroll")                                                \
                for (int g = 0; g < 3; ++g) {                                    \
                    ldsm_x2(br, sb + (unsigned)SC_B +                            \
                        (unsigned)((g*8 + l7)*2048) + (unsigned)(bus*16));       \
                    mma_fp16(c[g], ah, br);                                      \
                }                                                                \
            }                                                                    \
        }
        SCAN_CHUNK(0, 3)
        SCAN_CHUNK(1, 2)
        SCAN_CHUNK(2, 1)
        SCAN_CHUNK(3, 0)
        #undef SCAN_CHUNK

        // scatter partials to red[wq][g][b][ol]  (aliases chunk 0; reads done)
        __syncthreads();
        {
            int row = wm*16 + (lane >> 2);
            int col = (lane & 3) * 2;
            float* rq = red + wq*1536;
            #pragma unroll
            for (int g = 0; g < 3; ++g) {
                float* rg = rq + g*512;
                rg[row*8 + col]         = c[g][0];
                rg[row*8 + col + 1]     = c[g][1];
                rg[(row+8)*8 + col]     = c[g][2];
                rg[(row+8)*8 + col + 1] = c[g][3];
            }
        }
        __syncthreads();

        // pointwise GRU update (reduce over 4 k-quarters)
        {
            int base = b0o*8 + ol0;
            float s0 = red[base]          + red[1536 + base]
                     + red[3072 + base]   + red[4608 + base];
            float s1 = red[512 + base]    + red[1536 + 512 + base]
                     + red[3072 + 512 + base] + red[4608 + 512 + base];
            float s2 = red[1024 + base]   + red[1536 + 1024 + base]
                     + red[3072 + 1024 + base] + red[4608 + 1024 + base];
            float r  = 1.f / (1.f + __expf(-(gi0[0] + s0 + bh0v[0])));
            float z  = 1.f / (1.f + __expf(-(gi0[1] + s1 + bh0v[1])));
            float na = gi0[2] + r * (s2 + bh0v[2]);
            float te = __expf(2.f * na);
            float n  = 1.f - 2.f / (te + 1.f);
            float hn = (1.f - z) * n + z * hold0;
            __half hb = __float2half_rn(hn);
            nhh[(size_t)b0o*H + o0 + ol0] = hb;
            nhl[(size_t)b0o*H + o0 + ol0] = __float2half_rn((hn - __half2float(hb)) * 1024.f);
        }

        // two-level tree grid barrier (acq_rel, monotone counters)
        __syncthreads();
        if (tid == 0) {
            unsigned tgt = (unsigned)(t + 1);
            unsigned old;
            asm volatile("atom.add.acq_rel.gpu.u32 %0, [%1], 1;"
                         : "=r"(old) : "l"(&g_leaf[leaf*32]) : "memory");
            if (old == tgt*8u - 1u) {
                unsigned rold;
                asm volatile("atom.add.acq_rel.gpu.u32 %0, [%1], 1;"
                             : "=r"(rold) : "l"(&g_root) : "memory");
                if (rold == tgt*16u - 1u) {
                    asm volatile("st.release.gpu.u32 [%0], %1;" :: "l"(&g_gen), "r"(tgt) : "memory");
                }
            }
            unsigned cur;
            do {
                asm volatile("ld.acquire.gpu.u32 %0, [%1];" : "=r"(cur) : "l"(&g_gen) : "memory");
            } while (cur < tgt);
        }
        __syncthreads();
    }
}

// ---------------- final FC + ReLU ----------------
__global__ void fc_kernel(const float* __restrict__ Wfc,
                          const float* __restrict__ bfc,
                          float* __restrict__ out) {
    int idx = blockIdx.x * blockDim.x + threadIdx.x;
    if (idx >= B * NC) return;
    int b = idx / NC, c = idx - b * NC;
    const __half* hh = g_hh[0] + (size_t)b * H;   // T even -> final in buffer 0
    const __half* hl = g_hl[0] + (size_t)b * H;
    float s = bfc[c];
    for (int k = 0; k < H; k += 8) {
        uint4 va = *(const uint4*)(hh + k);
        uint4 vb = *(const uint4*)(hl + k);
        const __half* pa = (const __half*)&va;
        const __half* pb = (const __half*)&vb;
        #pragma unroll
        for (int e = 0; e < 8; ++e) {
            float hv = __half2float(pa[e]) + __half2float(pb[e]) * 9.765625e-4f;
            s += hv * Wfc[(size_t)(k + e) * NC + c];
        }
    }
    out[idx] = fmaxf(s, 0.f);
}

// ---------------- launcher ----------------
extern "C" void kernel_launch(void* const* d_in, const int* in_sizes, int n_in,
                              void* d_out, int out_size) {
    (void)in_sizes; (void)n_in; (void)out_size;
    const float* x    = (const float*)d_in[0];
    const float* c0   = (const float*)d_in[1];
    const float* c1   = (const float*)d_in[2];
    const float* c2   = (const float*)d_in[3];
    const float* c3   = (const float*)d_in[4];
    const float* bi   = (const float*)d_in[5];
    const float* U    = (const float*)d_in[6];
    const float* bh   = (const float*)d_in[7];
    const float* Wfc  = (const float*)d_in[8];
    const float* bfc  = (const float*)d_in[9];

    cudaFuncSetAttribute(ttA_kernel,  cudaFuncAttributeMaxDynamicSharedMemorySize, TTA_SMEM);
    cudaFuncSetAttribute(ttB_kernel,  cudaFuncAttributeMaxDynamicSharedMemorySize, TTB_SMEM);
    cudaFuncSetAttribute(scan_kernel, cudaFuncAttributeMaxDynamicSharedMemorySize, SCAN_SMEM);

    init_kernel<<<64, 256>>>();
    build_M_kernel<<<16, 256>>>(c0, c1, c2, c3);
    build_M34T_kernel<<<24, 256>>>();
    build_UT_kernel<<<dim3(96, 32), dim3(32, 8)>>>(U);
    ttA_kernel<<<BT/8, 256, TTA_SMEM>>>(x);
    ttB_kernel<<<dim3(BT*16/128, 3), 256, TTB_SMEM>>>(bi);
    scan_kernel<<<SCAN_BLOCKS, SCAN_THREADS, SCAN_SMEM>>>(bh);
    fc_kernel<<<(B * NC + 255) / 256, 256>>>(Wfc, bfc, (float*)d_out);
}

// round 17
// speedup vs baseline: 1.9770x; 1.1765x over previous
#include <cuda_runtime.h>
#include <cuda_fp16.h>
#include <cuda_bf16.h>
#include <math.h>
#include <stdint.h>

typedef unsigned long long ull;

// ---------------- problem constants ----------------
#define B   64
#define T   256
#define D   2048
#define H   1024
#define G3  3072
#define NC  1000
#define BT  (B*T)

#define CP_ASYNC16(dst, src) \
    asm volatile("cp.async.cg.shared.global [%0], [%1], 16;" :: "r"(dst), "l"(src))
#define CP_COMMIT() asm volatile("cp.async.commit_group;")
#define CP_WAIT0()  asm volatile("cp.async.wait_group 0;")

// ---------------- warp MMA helpers ----------------
__device__ __forceinline__ void ldsm_x4(uint32_t* r, unsigned addr) {
    asm volatile("ldmatrix.sync.aligned.m8n8.x4.shared.b16 {%0,%1,%2,%3}, [%4];"
        : "=r"(r[0]), "=r"(r[1]), "=r"(r[2]), "=r"(r[3]) : "r"(addr));
}
__device__ __forceinline__ void ldsm_x2(uint32_t* r, unsigned addr) {
    asm volatile("ldmatrix.sync.aligned.m8n8.x2.shared.b16 {%0,%1}, [%2];"
        : "=r"(r[0]), "=r"(r[1]) : "r"(addr));
}
__device__ __forceinline__ void ldsm_x2t(uint32_t* r, unsigned addr) {
    asm volatile("ldmatrix.sync.aligned.m8n8.x2.trans.shared.b16 {%0,%1}, [%2];"
        : "=r"(r[0]), "=r"(r[1]) : "r"(addr));
}
__device__ __forceinline__ void mma_fp16(float* c, const uint32_t* a, const uint32_t* b) {
    asm volatile(
        "mma.sync.aligned.m16n8k16.row.col.f32.f16.f16.f32 "
        "{%0,%1,%2,%3}, {%4,%5,%6,%7}, {%8,%9}, {%0,%1,%2,%3};"
        : "+f"(c[0]), "+f"(c[1]), "+f"(c[2]), "+f"(c[3])
        : "r"(a[0]), "r"(a[1]), "r"(a[2]), "r"(a[3]), "r"(b[0]), "r"(b[1]));
}

// ---------------- device scratch ----------------
__device__ __align__(16) float  g_M2 [3*2048];
__device__ __align__(16) __half g_M2img[192*64];
__device__ __align__(16) float  g_M34[3*16384];
__device__ __align__(16) __half g_M34h[3*16384];
__device__ __align__(16) __half g_M34l[3*16384];
__device__ __align__(16) __half g_UTf[(size_t)G3*H];          // U^T fp16 [j][k]
__device__ __align__(16) __half g_P  [(size_t)BT*12288];
__device__ __align__(16) float  g_gi [(size_t)BT*G3];         // [t][b][3H]
__device__ __align__(16) __half g_hh[2][B*H];
__device__ __align__(16) __half g_hl[2][B*H];
// group barriers: counters at g_bar[bg*32], gens at g_bar[(4+bg)*32]
__device__ unsigned g_bar[8*32];

// ---------------- init ----------------
__global__ void init_kernel() {
    int idx = blockIdx.x * blockDim.x + threadIdx.x;
    unsigned* hh = (unsigned*)g_hh[0];
    unsigned* hl = (unsigned*)g_hl[0];
    for (int i = idx; i < B*H/2; i += gridDim.x * blockDim.x) { hh[i] = 0u; hl[i] = 0u; }
    if (idx < 8*32) g_bar[idx] = 0u;
}

// ---------------- build M2, M34 (grid-parallel) ----------------
__global__ void build_M_kernel(const float* __restrict__ c0,
                               const float* __restrict__ c1,
                               const float* __restrict__ c2,
                               const float* __restrict__ c3) {
    int gid = blockIdx.x * blockDim.x + threadIdx.x;
    int nt  = gridDim.x * blockDim.x;
    for (int idx = gid; idx < 3*2048; idx += nt) {
        int r2 = idx & 3, o2 = (idx>>2)&3, o1 = (idx>>4)&3;
        int i2 = (idx>>6)&7, i1 = (idx>>9)&3, g = idx>>11;
        float s = 0.f;
        #pragma unroll
        for (int r1 = 0; r1 < 4; ++r1)
            s += c0[g*64 + i1*16 + o1*4 + r1] *
                 c1[g*512 + r1*128 + i2*16 + o2*4 + r2];
        g_M2[idx] = s;
    }
    for (int idx = gid; idx < 3*16384; idx += nt) {
        int o4 = idx & 7, o3 = (idx>>3)&7, i4 = (idx>>6)&7;
        int i3 = (idx>>9)&7, r2 = (idx>>12)&3, g = idx>>14;
        float s = 0.f;
        #pragma unroll
        for (int r3 = 0; r3 < 4; ++r3)
            s += c2[g*1024 + r2*256 + i3*32 + o3*4 + r3] *
                 c3[g*256  + r3*64  + i4*8  + o4];
        g_M34[idx] = s;
    }
}

// post-pass: M34 -> [g][n][k] fp16 hi/lo; M2 -> swizzled fp16 A-image
__global__ void build_M34T_kernel() {
    int gid = blockIdx.x * blockDim.x + threadIdx.x;
    int nt  = gridDim.x * blockDim.x;
    for (int idx = gid; idx < 3*16384; idx += nt) {
        int g = idx >> 14, rem = idx & 16383;
        int n = rem >> 8, k = rem & 255;
        float v = g_M34[g*16384 + k*64 + n];
        __half hi = __float2half_rn(v);
        g_M34h[idx] = hi;
        g_M34l[idx] = __float2half_rn(v - __half2float(hi));
    }
    for (int idx = gid; idx < 192*32; idx += nt) {
        int r = idx >> 5, k = idx & 31;
        float v = g_M2[(r >> 6)*2048 + k*64 + (r & 63)];
        int us = (k >> 3) ^ (r & 7);
        g_M2img[r*64 + us*8 + (k & 7)] = __float2half_rn(v);
    }
}

// ---------------- transpose U [H,G3] -> UT fp16 [G3,H] ----------------
__global__ void build_UT_kernel(const float* __restrict__ U) {
    __shared__ float s[32][33];
    int j0 = blockIdx.x * 32;
    int k0 = blockIdx.y * 32;
    int tx = threadIdx.x, ty = threadIdx.y;
    #pragma unroll
    for (int r = ty; r < 32; r += 8)
        s[r][tx] = U[(size_t)(k0 + r) * G3 + j0 + tx];
    __syncthreads();
    #pragma unroll
    for (int r = ty; r < 32; r += 8)
        g_UTf[(size_t)(j0 + r) * H + k0 + tx] = __float2half_rn(s[tx][r]);
}

// ---------------- TT stage A: HMMA ----------------
#define SC_M2 0                        // 192 rows x 128B = 24576
#define SC_X  24576                    // 8 bt x 4096
#define TTA_SMEM (24576 + 8*4096)      // 57344
__global__ void __launch_bounds__(256)
ttA_kernel(const float* __restrict__ X) {
    extern __shared__ __align__(1024) char smA[];
    const unsigned sb = (unsigned)__cvta_generic_to_shared(smA);
    const int tid = threadIdx.x;
    const int bt0 = blockIdx.x * 8;

    #pragma unroll
    for (int j = 0; j < 6; ++j) {
        int i = tid + j*256;
        CP_ASYNC16(sb + (unsigned)(i*16), (const char*)g_M2img + i*16);
    }
    CP_COMMIT();

    #pragma unroll
    for (int j = 0; j < 16; ++j) {
        int f  = tid + j*256;
        int bt = f >> 9;
        int v  = f & 511;
        int k  = v >> 4;
        int q0 = (v & 15) << 2;
        float4 xv = *((const float4*)(X + (size_t)(bt0 + bt)*D) + (k*16 + (v & 15)));
        __half2 h01 = __floats2half2_rn(xv.x, xv.y);
        __half2 h23 = __floats2half2_rn(xv.z, xv.w);
        int us = (q0 >> 3) ^ (k & 7);
        char* dst = smA + SC_X + bt*4096 + k*128 + us*16 + (q0 & 4)*2;
        *(__half2*)(dst)     = h01;
        *(__half2*)(dst + 4) = h23;
    }
    CP_WAIT0();
    __syncthreads();

    const int w    = tid >> 5;
    const int lane = tid & 31;
    const unsigned xbase = sb + (unsigned)SC_X + (unsigned)w*4096u;
    __half* Pb = g_P + (size_t)(bt0 + w) * 12288;

    const int l15 = lane & 15;
    const int l16 = lane >> 4;
    const int lq  = (lane & 3) * 2;
    const int lr  = lane >> 2;

    for (int rt = 0; rt < 6; ++rt) {
        float c[2][8][4];
        #pragma unroll
        for (int mt = 0; mt < 2; ++mt)
            #pragma unroll
            for (int nt = 0; nt < 8; ++nt)
                #pragma unroll
                for (int e = 0; e < 4; ++e) c[mt][nt][e] = 0.f;

        #pragma unroll
        for (int kh = 0; kh < 2; ++kh) {
            uint32_t a[2][4];
            #pragma unroll
            for (int mt = 0; mt < 2; ++mt) {
                int r = rt*32 + mt*16 + l15;
                int u = kh*2 + l16;
                int us = u ^ (r & 7);
                ldsm_x4(a[mt], sb + (unsigned)(SC_M2 + r*128 + us*16));
            }
            #pragma unroll
            for (int nt = 0; nt < 8; ++nt) {
                uint32_t b[2];
                int k  = kh*16 + l15;
                int us = nt ^ (k & 7);
                ldsm_x2t(b, xbase + (unsigned)(k*128 + us*16));
                mma_fp16(c[0][nt], a[0], b);
                mma_fp16(c[1][nt], a[1], b);
            }
        }

        #pragma unroll
        for (int mt = 0; mt < 2; ++mt) {
            int r0 = rt*32 + mt*16 + lr;
            int r1 = r0 + 8;
            int off0 = ((r0 >> 6)*16 + ((r0 >> 2) & 15))*256 + (r0 & 3)*64;
            int off1 = ((r1 >> 6)*16 + ((r1 >> 2) & 15))*256 + (r1 & 3)*64;
            #pragma unroll
            for (int nt = 0; nt < 8; ++nt) {
                int q = nt*8 + lq;
                *(__half2*)(Pb + off0 + q) = __floats2half2_rn(c[mt][nt][0], c[mt][nt][1]);
                *(__half2*)(Pb + off1 + q) = __floats2half2_rn(c[mt][nt][2], c[mt][nt][3]);
            }
        }
    }
}

// ---------------- TT stage B: HMMA (unchanged) ----------------
#define TTB_SMEM (65536 + 32768 + 32768)   // A 64KB | Bh 32KB | Bl 32KB
__global__ void __launch_bounds__(256)
ttB_kernel(const float* __restrict__ bi) {
    extern __shared__ __align__(1024) char smB[];
    const unsigned sb = (unsigned)__cvta_generic_to_shared(smB);
    const int tid = threadIdx.x;
    const int g   = blockIdx.y;
    const int m0  = blockIdx.x * 128;

    for (int i = tid; i < 4096; i += 256) {
        int r = i >> 5, u = i & 31;
        int us = (u & ~7) | ((u & 7) ^ (r & 7));
        int m = m0 + r;
        const __half* src = g_P + ((size_t)(m >> 4)*48 + g*16 + (m & 15))*256 + u*8;
        CP_ASYNC16(sb + (unsigned)(r*512 + us*16), src);
    }
    for (int i = tid; i < 2048; i += 256) {
        int n = i >> 5, u = i & 31;
        int us = (u & ~7) | ((u & 7) ^ (n & 7));
        const __half* s1 = g_M34h + ((size_t)g*64 + n)*256 + u*8;
        const __half* s2 = g_M34l + ((size_t)g*64 + n)*256 + u*8;
        CP_ASYNC16(sb + 65536u + (unsigned)(n*512 + us*16), s1);
        CP_ASYNC16(sb + 98304u + (unsigned)(n*512 + us*16), s2);
    }
    CP_COMMIT(); CP_WAIT0();
    __syncthreads();

    const int wid = tid >> 5, lane = tid & 31;
    const int wm = wid & 3, wn = wid >> 2;
    const int lrow = lane & 15, lk = lane >> 4;

    float c[2][4][4];
    #pragma unroll
    for (int ms = 0; ms < 2; ++ms)
        #pragma unroll
        for (int j = 0; j < 4; ++j)
            #pragma unroll
            for (int e = 0; e < 4; ++e) c[ms][j][e] = 0.f;

    #pragma unroll
    for (int ks = 0; ks < 16; ++ks) {
        const int u = ks*2 + lk;
        uint32_t a[2][4], bh4[2][4], bl4[2][4];
        #pragma unroll
        for (int ms = 0; ms < 2; ++ms) {
            int r = wm*32 + ms*16 + lrow;
            int us = (u & ~7) | ((u & 7) ^ (r & 7));
            ldsm_x4(a[ms], sb + (unsigned)(r*512 + us*16));
        }
        #pragma unroll
        for (int ns = 0; ns < 2; ++ns) {
            int n = wn*32 + ns*16 + lrow;
            int us = (u & ~7) | ((u & 7) ^ (n & 7));
            ldsm_x4(bh4[ns], sb + 65536u + (unsigned)(n*512 + us*16));
            ldsm_x4(bl4[ns], sb + 98304u + (unsigned)(n*512 + us*16));
        }
        #pragma unroll
        for (int ms = 0; ms < 2; ++ms)
            #pragma unroll
            for (int j = 0; j < 4; ++j) {
                uint32_t bfh[2] = { bh4[j>>1][j&1], bh4[j>>1][(j&1)+2] };
                uint32_t bfl[2] = { bl4[j>>1][j&1], bl4[j>>1][(j&1)+2] };
                mma_fp16(c[ms][j], a[ms], bfh);
                mma_fp16(c[ms][j], a[ms], bfl);
            }
    }

    #pragma unroll
    for (int ms = 0; ms < 2; ++ms) {
        #pragma unroll
        for (int j = 0; j < 4; ++j) {
            int nn = wn*32 + j*8 + (lane & 3)*2;
            #pragma unroll
            for (int half = 0; half < 2; ++half) {
                int r = wm*32 + ms*16 + (lane >> 2) + half*8;
                int m = m0 + r;
                int bt = m >> 4, oo = m & 15;
                int bb = bt >> 8, tt = bt & 255;
                const float* bp = bi + g*1024 + oo*64 + nn;
                float2 v;
                v.x = c[ms][j][half*2]     + bp[0];
                v.y = c[ms][j][half*2 + 1] + bp[1];
                *(float2*)(g_gi + ((size_t)tt*B + bb)*G3 + g*1024 + oo*64 + nn) = v;
            }
        }
    }
}

// ---------------- persistent scan v3: batch-partitioned, group barriers ----
// 128 blocks = 4 batch-groups(16 b) x 32 o-groups(32 o). 512 thr, 16 warps =
// 4 k-quarters x 4 n-subgroups. U slice (96 n-rows x 1024 k fp16, 192KB)
// resident in smem; h stage = 32 KB/step, single commit. Barrier per bg (32 blocks).
#define SCAN_BLOCKS 128
#define SCAN_THREADS 512
#define SC_B  0                      // 96 x 2048B = 196608
#define SC_A  196608                 // 32768 (aliased by red, 25344B)
#define SCAN_SMEM (196608 + 32768)   // 229376

__global__ void __launch_bounds__(SCAN_THREADS, 1)
scan_kernel(const float* __restrict__ bh) {
    extern __shared__ __align__(1024) char smem[];
    const unsigned sb = (unsigned)__cvta_generic_to_shared(smem);
    const int tid  = threadIdx.x;
    const int wid  = tid >> 5;
    const int lane = tid & 31;
    const int bg   = blockIdx.x >> 5;    // batch group (16 b)
    const int og   = blockIdx.x & 31;    // o group (32 o)
    const int o0   = og * 32;
    const int b0   = bg * 16;
    const int wq   = wid & 3;            // k-quarter
    const int wn   = wid >> 2;           // n-subgroup (8 o per gate)

    // stage B = UT slice fp16 once: rows n = g*32+ol, k 0..1023, swizzled
    for (int i = tid; i < 96*128; i += SCAN_THREADS) {
        int n = i >> 7, u = i & 127;
        int us = (u & ~7) | ((u & 7) ^ (n & 7));
        int g = n >> 5, ol = n & 31;
        size_t src = ((size_t)(g*H + o0 + ol))*H + (size_t)u*8;
        *(uint4*)(smem + SC_B + n*2048 + us*16) = *(const uint4*)(g_UTf + src);
    }
    __syncthreads();

    const int arow  = lane & 15;
    const int kadd8 = lane >> 4;
    const int arow7 = arow & 7;
    const int l7    = lane & 7;
    const int bk8   = (lane >> 3) & 1;

    // pointwise: one output per thread
    const int pb = tid >> 5;     // local b 0..15
    const int po = tid & 31;     // local o 0..31
    float bhv[3];
    #pragma unroll
    for (int g = 0; g < 3; ++g) bhv[g] = bh[g*H + o0 + po];

    float* red = (float*)(smem + SC_A);   // [wq(4)][g(3)][b(16) stride 33][o(32)]

    unsigned* barc = &g_bar[bg*32];
    unsigned* barg = &g_bar[(4 + bg)*32];

    for (int t = 0; t < T; ++t) {
        const __half* hh = g_hh[t & 1];
        const __half* hl = g_hl[t & 1];
        __half* nhh = g_hh[(t & 1) ^ 1];
        __half* nhl = g_hl[(t & 1) ^ 1];

        // stage A: h[b0..b0+15][0..1023] fp16, one commit
        #pragma unroll
        for (int j = 0; j < 4; ++j) {
            int i = tid + j*SCAN_THREADS;
            int b = i >> 7, u = i & 127;
            int us = (u & ~7) | ((u & 7) ^ (b & 7));
            CP_ASYNC16(sb + (unsigned)SC_A + (unsigned)(b*2048 + us*16),
                       hh + (size_t)(b0 + b)*H + u*8);
        }
        CP_COMMIT();

        float gi0[3], hold0;
        {
            const float* gp0 = g_gi + ((size_t)t*B + b0 + pb)*G3 + o0 + po;
            #pragma unroll
            for (int g = 0; g < 3; ++g) gi0[g] = __ldg(gp0 + g*H);
            hold0 = __half2float(hh[(size_t)(b0 + pb)*H + o0 + po])
                  + __half2float(hl[(size_t)(b0 + pb)*H + o0 + po]) * 9.765625e-4f;
        }

        float c[3][4];
        #pragma unroll
        for (int g = 0; g < 3; ++g)
            #pragma unroll
            for (int e = 0; e < 4; ++e) c[g][e] = 0.f;

        CP_WAIT0();
        __syncthreads();

        // compute: warp covers ks = wq*16 .. +15
        #pragma unroll
        for (int j = 0; j < 16; ++j) {
            int ks = wq*16 + j;
            uint32_t ah[4], br[2];
            int u  = ks*2 + kadd8;
            int us = (u & ~7) | ((u & 7) ^ arow7);
            ldsm_x4(ah, sb + (unsigned)SC_A + (unsigned)(arow*2048 + us*16));
            int kg  = ks*2 + bk8;
            int bus = (kg & ~7) | ((kg & 7) ^ l7);
            #pragma unroll
            for (int g = 0; g < 3; ++g) {
                int n = g*32 + wn*8 + l7;
                ldsm_x2(br, sb + (unsigned)SC_B + (unsigned)(n*2048 + bus*16));
                mma_fp16(c[g], ah, br);
            }
        }

        // scatter partials to red[wq][g][row(stride 33)][o]
        __syncthreads();
        {
            int row  = lane >> 2;
            int colo = wn*8 + (lane & 3)*2;
            float* rq = red + wq*1584;
            #pragma unroll
            for (int g = 0; g < 3; ++g) {
                float* rg = rq + g*528;
                rg[row*33 + colo]           = c[g][0];
                rg[row*33 + colo + 1]       = c[g][1];
                rg[(row+8)*33 + colo]       = c[g][2];
                rg[(row+8)*33 + colo + 1]   = c[g][3];
            }
        }
        __syncthreads();

        // pointwise GRU update (reduce over 4 k-quarters)
        {
            int base = pb*33 + po;
            float s0 = red[base]        + red[1584 + base]
                     + red[3168 + base] + red[4752 + base];
            float s1 = red[528 + base]        + red[1584 + 528 + base]
                     + red[3168 + 528 + base] + red[4752 + 528 + base];
            float s2 = red[1056 + base]        + red[1584 + 1056 + base]
                     + red[3168 + 1056 + base] + red[4752 + 1056 + base];
            float r  = 1.f / (1.f + __expf(-(gi0[0] + s0 + bhv[0])));
            float z  = 1.f / (1.f + __expf(-(gi0[1] + s1 + bhv[1])));
            float na = gi0[2] + r * (s2 + bhv[2]);
            float te = __expf(2.f * na);
            float n  = 1.f - 2.f / (te + 1.f);
            float hn = (1.f - z) * n + z * hold0;
            __half hb = __float2half_rn(hn);
            nhh[(size_t)(b0 + pb)*H + o0 + po] = hb;
            nhl[(size_t)(b0 + pb)*H + o0 + po] =
                __float2half_rn((hn - __half2float(hb)) * 1024.f);
        }

        // per-group barrier (32 blocks of this batch group)
        __syncthreads();
        if (tid == 0) {
            unsigned tgt = (unsigned)(t + 1);
            unsigned old;
            asm volatile("atom.add.acq_rel.gpu.u32 %0, [%1], 1;"
                         : "=r"(old) : "l"(barc) : "memory");
            if (old == tgt*32u - 1u) {
                asm volatile("st.release.gpu.u32 [%0], %1;" :: "l"(barg), "r"(tgt) : "memory");
            }
            unsigned cur;
            do {
                asm volatile("ld.acquire.gpu.u32 %0, [%1];" : "=r"(cur) : "l"(barg) : "memory");
            } while (cur < tgt);
        }
        __syncthreads();
    }
}

// ---------------- final FC + ReLU ----------------
__global__ void fc_kernel(const float* __restrict__ Wfc,
                          const float* __restrict__ bfc,
                          float* __restrict__ out) {
    int idx = blockIdx.x * blockDim.x + threadIdx.x;
    if (idx >= B * NC) return;
    int b = idx / NC, c = idx - b * NC;
    const __half* hh = g_hh[0] + (size_t)b * H;   // T even -> final in buffer 0
    const __half* hl = g_hl[0] + (size_t)b * H;
    float s = bfc[c];
    for (int k = 0; k < H; k += 8) {
        uint4 va = *(const uint4*)(hh + k);
        uint4 vb = *(const uint4*)(hl + k);
        const __half* pa = (const __half*)&va;
        const __half* pb = (const __half*)&vb;
        #pragma unroll
        for (int e = 0; e < 8; ++e) {
            float hv = __half2float(pa[e]) + __half2float(pb[e]) * 9.765625e-4f;
            s += hv * Wfc[(size_t)(k + e) * NC + c];
        }
    }
    out[idx] = fmaxf(s, 0.f);
}

// ---------------- launcher ----------------
extern "C" void kernel_launch(void* const* d_in, const int* in_sizes, int n_in,
                              void* d_out, int out_size) {
    (void)in_sizes; (void)n_in; (void)out_size;
    const float* x    = (const float*)d_in[0];
    const float* c0   = (const float*)d_in[1];
    const float* c1   = (const float*)d_in[2];
    const float* c2   = (const float*)d_in[3];
    const float* c3   = (const float*)d_in[4];
    const float* bi   = (const float*)d_in[5];
    const float* U    = (const float*)d_in[6];
    const float* bh   = (const float*)d_in[7];
    const float* Wfc  = (const float*)d_in[8];
    const float* bfc  = (const float*)d_in[9];

    cudaFuncSetAttribute(ttA_kernel,  cudaFuncAttributeMaxDynamicSharedMemorySize, TTA_SMEM);
    cudaFuncSetAttribute(ttB_kernel,  cudaFuncAttributeMaxDynamicSharedMemorySize, TTB_SMEM);
    cudaFuncSetAttribute(scan_kernel, cudaFuncAttributeMaxDynamicSharedMemorySize, SCAN_SMEM);

    init_kernel<<<64, 256>>>();
    build_M_kernel<<<16, 256>>>(c0, c1, c2, c3);
    build_M34T_kernel<<<24, 256>>>();
    build_UT_kernel<<<dim3(96, 32), dim3(32, 8)>>>(U);
    ttA_kernel<<<BT/8, 256, TTA_SMEM>>>(x);
    ttB_kernel<<<dim3(BT*16/128, 3), 256, TTB_SMEM>>>(bi);
    scan_kernel<<<SCAN_BLOCKS, SCAN_THREADS, SCAN_SMEM>>>(bh);
    fc_kernel<<<(B * NC + 255) / 256, 256>>>(Wfc, bfc, (float*)d_out);
}